// round 1
// baseline (speedup 1.0000x reference)
#include <cuda_runtime.h>
#include <math.h>

#define NB 16
#define NPIX (512*512)
#define NP 10
#define BPB 64            // blocks per batch
#define THREADS 128
#define NSLOT 30          // 3 heads * 10 query slots
#define ITERS (NPIX/4/(BPB*THREADS))  // 8 float4-groups per thread

// scratch (graph-capture safe: static device globals, no allocation)
__device__ float g_part[NB][BPB][NSLOT][3];  // m, s, sv partials per block
__device__ float g_comb[NB][NSLOT][2];       // final s, sv per (b, head*10+distinct_idx)

// ---------------------------------------------------------------------------
// Kernel 1: stream x once; per pixel compute LN -> k,v (3x3 proj folded with
// LN affine); online softmax accumulation for each (head, distinct-q) slot.
// ---------------------------------------------------------------------------
__global__ void __launch_bounds__(THREADS) k_main(
    const float* __restrict__ x, const float* __restrict__ qp,
    const float* __restrict__ ln1w, const float* __restrict__ ln1b,
    const float* __restrict__ Wk, const float* __restrict__ bk,
    const float* __restrict__ Wv, const float* __restrict__ bv)
{
    __shared__ float s_da[3][NP];
    __shared__ int   s_cnt[3];
    __shared__ float s_red[4][NSLOT][3];

    const int b    = blockIdx.x / BPB;
    const int blk  = blockIdx.x % BPB;
    const int t    = threadIdx.x;
    const int lane = t & 31;
    const int warp = t >> 5;

    // Build per-head distinct-q lists (q_param is batch-broadcast). SCALE = 1 (HEAD_DIM=1).
    if (t == 0) {
        for (int h = 0; h < 3; h++) {
            int cnt = 0;
            for (int j = 0; j < NP; j++) {
                float v = qp[j*3 + h];
                int f = -1;
                for (int c = 0; c < cnt; c++) if (s_da[h][c] == v) { f = c; break; }
                if (f < 0) { s_da[h][cnt] = v; cnt++; }
            }
            for (int j = cnt; j < NP; j++) s_da[h][j] = 0.0f;
            s_cnt[h] = cnt;
        }
    }
    __syncthreads();

    // Fold LayerNorm affine into the k/v projections:
    // k_h = inv * (d0*Ak[h][0] + d1*Ak[h][1] + d2*Ak[h][2]) + Bk[h]
    float Ak[3][3], Bk[3], Av[3][3], Bv[3];
    #pragma unroll
    for (int h = 0; h < 3; h++) {
        float sk = bk[h], sv0 = bv[h];
        #pragma unroll
        for (int c = 0; c < 3; c++) {
            float wkv = Wk[h*3+c], wvv = Wv[h*3+c];
            float lw = ln1w[c], lb = ln1b[c];
            Ak[h][c] = wkv * lw;
            Av[h][c] = wvv * lw;
            sk  += wkv * lb;
            sv0 += wvv * lb;
        }
        Bk[h] = sk; Bv[h] = sv0;
    }

    float da[3][NP]; int cnt[3];
    #pragma unroll
    for (int h = 0; h < 3; h++) {
        cnt[h] = s_cnt[h];
        #pragma unroll
        for (int j = 0; j < NP; j++) da[h][j] = s_da[h][j];
    }

    // online-softmax accumulators (compile-time indexed -> registers)
    float am[3][NP], as[3][NP], av[3][NP];
    #pragma unroll
    for (int h = 0; h < 3; h++)
        #pragma unroll
        for (int j = 0; j < NP; j++) { am[h][j] = -1e30f; as[h][j] = 0.f; av[h][j] = 0.f; }

    const float4* p0 = (const float4*)(x + (size_t)b * 3 * NPIX);
    const float4* p1 = p0 + NPIX/4;
    const float4* p2 = p0 + NPIX/2;
    const int g0 = blk*THREADS + t;

    #pragma unroll 2
    for (int it = 0; it < ITERS; it++) {
        int g = g0 + it*(BPB*THREADS);
        float4 r0 = p0[g], r1 = p1[g], r2 = p2[g];
        float c0[4] = {r0.x, r0.y, r0.z, r0.w};
        float c1[4] = {r1.x, r1.y, r1.z, r1.w};
        float c2[4] = {r2.x, r2.y, r2.z, r2.w};
        #pragma unroll
        for (int e = 0; e < 4; e++) {
            float x0 = c0[e], x1 = c1[e], x2 = c2[e];
            float mu  = (x0 + x1 + x2) * (1.0f/3.0f);
            float d0 = x0 - mu, d1 = x1 - mu, d2 = x2 - mu;
            float var = (d0*d0 + d1*d1 + d2*d2) * (1.0f/3.0f);
            float inv = rsqrtf(var + 1e-5f);
            float kh[3], vh[3];
            #pragma unroll
            for (int h = 0; h < 3; h++) {
                kh[h] = fmaf(inv, d0*Ak[h][0] + d1*Ak[h][1] + d2*Ak[h][2], Bk[h]);
                vh[h] = fmaf(inv, d0*Av[h][0] + d1*Av[h][1] + d2*Av[h][2], Bv[h]);
            }
            #pragma unroll
            for (int h = 0; h < 3; h++) {
                #pragma unroll
                for (int j = 0; j < NP; j++) {
                    if (j >= cnt[h]) break;   // uniform early-exit: only distinct q's do work
                    float l = da[h][j] * kh[h];
                    if (l > am[h][j]) {       // rare rescale path
                        float cc = __expf(am[h][j] - l);
                        as[h][j] = fmaf(as[h][j], cc, 1.0f);
                        av[h][j] = fmaf(av[h][j], cc, vh[h]);
                        am[h][j] = l;
                    } else {                  // common path: 1 exp
                        float e2 = __expf(l - am[h][j]);
                        as[h][j] += e2;
                        av[h][j] = fmaf(e2, vh[h], av[h][j]);
                    }
                }
            }
        }
    }

    // warp reduce: max -> rescale -> sum (deterministic, no atomics)
    #pragma unroll
    for (int h = 0; h < 3; h++) {
        #pragma unroll
        for (int j = 0; j < NP; j++) {
            float m = am[h][j];
            float M = m;
            #pragma unroll
            for (int off = 16; off > 0; off >>= 1)
                M = fmaxf(M, __shfl_xor_sync(0xffffffffu, M, off));
            float f  = __expf(m - M);
            float s  = as[h][j] * f;
            float sv = av[h][j] * f;
            #pragma unroll
            for (int off = 16; off > 0; off >>= 1) {
                s  += __shfl_xor_sync(0xffffffffu, s,  off);
                sv += __shfl_xor_sync(0xffffffffu, sv, off);
            }
            if (lane == 0) {
                s_red[warp][h*NP+j][0] = M;
                s_red[warp][h*NP+j][1] = s;
                s_red[warp][h*NP+j][2] = sv;
            }
        }
    }
    __syncthreads();
    if (t < NSLOT) {
        float M = -1e30f;
        #pragma unroll
        for (int w = 0; w < 4; w++) M = fmaxf(M, s_red[w][t][0]);
        float s = 0.f, sv = 0.f;
        #pragma unroll
        for (int w = 0; w < 4; w++) {
            float f = __expf(s_red[w][t][0] - M);
            s  = fmaf(s_red[w][t][1], f, s);
            sv = fmaf(s_red[w][t][2], f, sv);
        }
        g_part[b][blk][t][0] = M;
        g_part[b][blk][t][1] = s;
        g_part[b][blk][t][2] = sv;
    }
}

// ---------------------------------------------------------------------------
// Kernel 2: combine 64 block-partials per (batch, slot) into final s, sv.
// ---------------------------------------------------------------------------
__global__ void k_comb()
{
    const int b = blockIdx.x;
    const int lane = threadIdx.x & 31;
    const int w = threadIdx.x >> 5;           // 8 warps

    for (int slot = w; slot < NSLOT; slot += 8) {
        // each lane merges 2 of the 64 partials first
        float m1 = g_part[b][lane][slot][0];
        float s1 = g_part[b][lane][slot][1];
        float v1 = g_part[b][lane][slot][2];
        float m2 = g_part[b][lane+32][slot][0];
        float s2 = g_part[b][lane+32][slot][1];
        float v2 = g_part[b][lane+32][slot][2];
        float m = fmaxf(m1, m2);
        float f1 = __expf(m1 - m), f2 = __expf(m2 - m);
        float s  = s1*f1 + s2*f2;
        float sv = v1*f1 + v2*f2;

        float M = m;
        #pragma unroll
        for (int off = 16; off > 0; off >>= 1)
            M = fmaxf(M, __shfl_xor_sync(0xffffffffu, M, off));
        float f = __expf(m - M);
        s *= f; sv *= f;
        #pragma unroll
        for (int off = 16; off > 0; off >>= 1) {
            s  += __shfl_xor_sync(0xffffffffu, s,  off);
            sv += __shfl_xor_sync(0xffffffffu, sv, off);
        }
        if (lane == 0) {
            g_comb[b][slot][0] = s;
            g_comb[b][slot][1] = sv;
        }
    }
}

// ---------------------------------------------------------------------------
// Kernel 3: epilogue. o = softmax(qk)v per (b,param) -> Wp -> LN2 -> SiLU FFN
// -> residual -> gamma/color heads. 160 threads total.
// ---------------------------------------------------------------------------
__global__ void k_epi(
    const float* __restrict__ qp,
    const float* __restrict__ Wp, const float* __restrict__ bp,
    const float* __restrict__ ln2w, const float* __restrict__ ln2b,
    const float* __restrict__ W1, const float* __restrict__ b1,
    const float* __restrict__ W2, const float* __restrict__ b2,
    const float* __restrict__ Wg, const float* __restrict__ bg,
    const float* __restrict__ Wc, const float* __restrict__ bc,
    const float* __restrict__ gb, const float* __restrict__ cb,
    float* __restrict__ out)
{
    int t = threadIdx.x;
    if (t >= NB*NP) return;
    int b = t / NP, qi = t % NP;

    float o[3];
    #pragma unroll
    for (int h = 0; h < 3; h++) {
        // replicate kernel-1's first-occurrence distinct indexing
        float list[NP]; int cnt2 = 0; int idx = 0;
        for (int j = 0; j <= qi; j++) {
            float v2 = qp[j*3 + h];
            int f = -1;
            for (int c = 0; c < cnt2; c++) if (list[c] == v2) { f = c; break; }
            if (f < 0) { list[cnt2] = v2; f = cnt2; cnt2++; }
            if (j == qi) idx = f;
        }
        float s  = g_comb[b][h*NP + idx][0];
        float sv = g_comb[b][h*NP + idx][1];
        o[h] = sv / s;   // HEAD_DIM=1: attention output = weighted mean of v
    }

    // o @ Wp.T + bp
    float op[3];
    #pragma unroll
    for (int e = 0; e < 3; e++)
        op[e] = bp[e] + o[0]*Wp[e*3+0] + o[1]*Wp[e*3+1] + o[2]*Wp[e*3+2];

    // LayerNorm over 3
    float mu = (op[0] + op[1] + op[2]) * (1.0f/3.0f);
    float d0 = op[0]-mu, d1 = op[1]-mu, d2 = op[2]-mu;
    float var = (d0*d0 + d1*d1 + d2*d2) * (1.0f/3.0f);
    float inv = rsqrtf(var + 1e-5f);
    float h2[3];
    h2[0] = d0*inv*ln2w[0] + ln2b[0];
    h2[1] = d1*inv*ln2w[1] + ln2b[1];
    h2[2] = d2*inv*ln2w[2] + ln2b[2];

    // FFN: silu(h2 @ W1.T + b1) @ W2.T + b2, residual with op
    float y[3] = { op[0] + b2[0], op[1] + b2[1], op[2] + b2[2] };
    #pragma unroll
    for (int f = 0; f < 12; f++) {
        float u = b1[f] + h2[0]*W1[f*3+0] + h2[1]*W1[f*3+1] + h2[2]*W1[f*3+2];
        float su = u / (1.0f + __expf(-u));
        y[0] += su * W2[0*12 + f];
        y[1] += su * W2[1*12 + f];
        y[2] += su * W2[2*12 + f];
    }

    if (qi == 0) {
        out[b] = bg[0] + gb[0] + y[0]*Wg[0] + y[1]*Wg[1] + y[2]*Wg[2];
    } else {
        int p = qi - 1;
        out[NB + b*9 + p] = bc[0] + y[0]*Wc[0] + y[1]*Wc[1] + y[2]*Wc[2] + cb[p];
    }
}

extern "C" void kernel_launch(void* const* d_in, const int* in_sizes, int n_in,
                              void* d_out, int out_size)
{
    const float* x    = (const float*)d_in[0];
    const float* qp   = (const float*)d_in[1];
    const float* ln1w = (const float*)d_in[2];
    const float* ln1b = (const float*)d_in[3];
    const float* Wk   = (const float*)d_in[4];
    const float* bk   = (const float*)d_in[5];
    const float* Wv   = (const float*)d_in[6];
    const float* bv   = (const float*)d_in[7];
    const float* Wp   = (const float*)d_in[8];
    const float* bp   = (const float*)d_in[9];
    const float* ln2w = (const float*)d_in[10];
    const float* ln2b = (const float*)d_in[11];
    const float* W1   = (const float*)d_in[12];
    const float* b1   = (const float*)d_in[13];
    const float* W2   = (const float*)d_in[14];
    const float* b2   = (const float*)d_in[15];
    const float* Wg   = (const float*)d_in[16];
    const float* bg   = (const float*)d_in[17];
    const float* Wc   = (const float*)d_in[18];
    const float* bc   = (const float*)d_in[19];
    const float* gb   = (const float*)d_in[20];
    const float* cb   = (const float*)d_in[21];
    float* out = (float*)d_out;

    k_main<<<NB*BPB, THREADS>>>(x, qp, ln1w, ln1b, Wk, bk, Wv, bv);
    k_comb<<<NB, 256>>>();
    k_epi<<<1, 160>>>(qp, Wp, bp, ln2w, ln2b, W1, b1, W2, b2,
                      Wg, bg, Wc, bc, gb, cb, out);
}

// round 2
// speedup vs baseline: 2.0410x; 2.0410x over previous
#include <cuda_runtime.h>
#include <math.h>

#define NB 16
#define NPIX (512*512)
#define NP 10
#define NSLOT 30
#define EPS 1e-5f

// fast kernel geometry
#define BPB 64
#define THREADS 256
#define STRIDE (BPB*THREADS)          // 16384 threads per batch
#define ITERS ((NPIX/4)/STRIDE)       // 4 float4-groups per channel per thread

// generic kernel geometry (fallback)
#define BPB_G 64
#define THR_G 128
#define ITERS_G ((NPIX/4)/(BPB_G*THR_G))  // 8

// ---- scratch (graph-capture safe device globals) ----
__device__ int   g_flag;                      // 1 = fast path valid
__device__ float c_Fk[3][3], c_Ck[3];         // q-folded, max-folded K coeffs
__device__ float c_Av[3][3], c_Bv[3];         // LN-folded V coeffs
__device__ float g_fast[NB][BPB][12];         // fast partials: per head {S,T0,T1,T2}
__device__ float g_part[NB][BPB_G][NSLOT][3]; // generic partials {m,s,sv}
__device__ float g_comb[NB][NSLOT][2];        // final {s, sv}

// ---------------------------------------------------------------------------
// Kernel 0: single thread — compute dispatch flag + folded coefficients ONCE,
// so all kernels agree bit-exactly on the dispatch decision.
// ---------------------------------------------------------------------------
__global__ void k_init(const float* __restrict__ qp,
                       const float* __restrict__ ln1w, const float* __restrict__ ln1b,
                       const float* __restrict__ Wk, const float* __restrict__ bk,
                       const float* __restrict__ Wv, const float* __restrict__ bv)
{
    int ok = 1;
    for (int h = 0; h < 3; h++) {
        float q = qp[h];
        for (int j = 1; j < NP; j++) ok &= (qp[j*3 + h] == q);
        float g = q * bk[h];
        float n2 = 0.f;
        for (int c = 0; c < 3; c++) {
            float f = q * Wk[h*3+c] * ln1w[c];
            c_Fk[h][c] = f;
            g += q * Wk[h*3+c] * ln1b[c];
            n2 += f * f;
        }
        float r = 1.7320509f * sqrtf(n2);   // sqrt(3) * ||Fk_row||  >= |dot(Fk,u)|
        c_Ck[h] = g - (g + r);              // = -r ; arg = dot(Fk,u) + g - M, M = g + r
        ok &= (2.f * r <= 60.f);            // exp range safe without running max

        // V fold: v_h = dot(Av_row, u) + Bv_h
        float bvv = bv[h];
        for (int c = 0; c < 3; c++) {
            c_Av[h][c] = Wv[h*3+c] * ln1w[c];
            bvv += Wv[h*3+c] * ln1b[c];
        }
        c_Bv[h] = bvv;
    }
    g_flag = ok;
}

// ---------------------------------------------------------------------------
// Kernel 1 (FAST): stream x once. Per pixel: LN -> u = (x-mu)*inv; per head:
// e = exp(dot(Fk,u) + Ck); accumulate S += e, T += e*u. No branches, 12 regs
// of accumulators. V projection deferred to the tail (linear in T,S).
// ---------------------------------------------------------------------------
__global__ void __launch_bounds__(THREADS, 4) k_fast(const float* __restrict__ x)
{
    if (!g_flag) return;

    __shared__ float s_red[THREADS/32][12];

    const int b    = blockIdx.x / BPB;
    const int blk  = blockIdx.x % BPB;
    const int t    = threadIdx.x;
    const int lane = t & 31;
    const int warp = t >> 5;

    float Fk[3][3], Ck[3];
    #pragma unroll
    for (int h = 0; h < 3; h++) {
        Ck[h] = c_Ck[h];
        #pragma unroll
        for (int c = 0; c < 3; c++) Fk[h][c] = c_Fk[h][c];
    }

    float S[3] = {0.f, 0.f, 0.f};
    float T[3][3];
    #pragma unroll
    for (int h = 0; h < 3; h++)
        #pragma unroll
        for (int c = 0; c < 3; c++) T[h][c] = 0.f;

    const float4* p0 = (const float4*)(x + (size_t)b * 3 * NPIX);
    const float4* p1 = p0 + NPIX/4;
    const float4* p2 = p0 + NPIX/2;

    int g = blk * THREADS + t;
    float4 a0 = __ldcs(p0 + g), a1 = __ldcs(p1 + g), a2 = __ldcs(p2 + g);

    #pragma unroll
    for (int it = 0; it < ITERS; it++) {
        float4 n0, n1, n2;
        if (it + 1 < ITERS) {
            int gn = g + STRIDE;
            n0 = __ldcs(p0 + gn); n1 = __ldcs(p1 + gn); n2 = __ldcs(p2 + gn);
        }
        float c0[4] = {a0.x, a0.y, a0.z, a0.w};
        float c1[4] = {a1.x, a1.y, a1.z, a1.w};
        float c2[4] = {a2.x, a2.y, a2.z, a2.w};
        #pragma unroll
        for (int e = 0; e < 4; e++) {
            float x0 = c0[e], x1 = c1[e], x2 = c2[e];
            float mu  = (x0 + x1 + x2) * (1.0f/3.0f);
            float d0 = x0 - mu, d1 = x1 - mu, d2 = x2 - mu;
            float var = (d0*d0 + d1*d1 + d2*d2) * (1.0f/3.0f);
            float inv = rsqrtf(var + EPS);
            float u0 = d0*inv, u1 = d1*inv, u2 = d2*inv;
            #pragma unroll
            for (int h = 0; h < 3; h++) {
                float arg = fmaf(u2, Fk[h][2], fmaf(u1, Fk[h][1], fmaf(u0, Fk[h][0], Ck[h])));
                float ee  = __expf(arg);
                S[h] += ee;
                T[h][0] = fmaf(ee, u0, T[h][0]);
                T[h][1] = fmaf(ee, u1, T[h][1]);
                T[h][2] = fmaf(ee, u2, T[h][2]);
            }
        }
        a0 = n0; a1 = n1; a2 = n2;
        g += STRIDE;
    }

    // pack 12 accumulators, warp reduce, then cross-warp in smem
    float acc[12];
    #pragma unroll
    for (int h = 0; h < 3; h++) {
        acc[h*4+0] = S[h]; acc[h*4+1] = T[h][0];
        acc[h*4+2] = T[h][1]; acc[h*4+3] = T[h][2];
    }
    #pragma unroll
    for (int f = 0; f < 12; f++) {
        float v = acc[f];
        #pragma unroll
        for (int off = 16; off > 0; off >>= 1)
            v += __shfl_xor_sync(0xffffffffu, v, off);
        acc[f] = v;
    }
    if (lane == 0) {
        #pragma unroll
        for (int f = 0; f < 12; f++) s_red[warp][f] = acc[f];
    }
    __syncthreads();
    if (t < 12) {
        float v = 0.f;
        #pragma unroll
        for (int w = 0; w < THREADS/32; w++) v += s_red[w][t];
        g_fast[b][blk][t] = v;
    }
}

// ---------------------------------------------------------------------------
// Kernel 2 (GENERIC fallback): previous passing online-softmax kernel,
// early-exits when the fast path is valid.
// ---------------------------------------------------------------------------
__global__ void __launch_bounds__(THR_G) k_generic(
    const float* __restrict__ x, const float* __restrict__ qp,
    const float* __restrict__ ln1w, const float* __restrict__ ln1b,
    const float* __restrict__ Wk, const float* __restrict__ bk,
    const float* __restrict__ Wv, const float* __restrict__ bv)
{
    if (g_flag) return;

    __shared__ float s_da[3][NP];
    __shared__ int   s_cnt[3];
    __shared__ float s_red[4][NSLOT][3];

    const int b    = blockIdx.x / BPB_G;
    const int blk  = blockIdx.x % BPB_G;
    const int t    = threadIdx.x;
    const int lane = t & 31;
    const int warp = t >> 5;

    if (t == 0) {
        for (int h = 0; h < 3; h++) {
            int cnt = 0;
            for (int j = 0; j < NP; j++) {
                float v = qp[j*3 + h];
                int f = -1;
                for (int c = 0; c < cnt; c++) if (s_da[h][c] == v) { f = c; break; }
                if (f < 0) { s_da[h][cnt] = v; cnt++; }
            }
            for (int j = cnt; j < NP; j++) s_da[h][j] = 0.0f;
            s_cnt[h] = cnt;
        }
    }
    __syncthreads();

    float Ak[3][3], Bk[3], Av[3][3], Bv[3];
    #pragma unroll
    for (int h = 0; h < 3; h++) {
        float sk = bk[h], sv0 = bv[h];
        #pragma unroll
        for (int c = 0; c < 3; c++) {
            float wkv = Wk[h*3+c], wvv = Wv[h*3+c];
            float lw = ln1w[c], lb = ln1b[c];
            Ak[h][c] = wkv * lw;
            Av[h][c] = wvv * lw;
            sk  += wkv * lb;
            sv0 += wvv * lb;
        }
        Bk[h] = sk; Bv[h] = sv0;
    }

    float da[3][NP]; int cnt[3];
    #pragma unroll
    for (int h = 0; h < 3; h++) {
        cnt[h] = s_cnt[h];
        #pragma unroll
        for (int j = 0; j < NP; j++) da[h][j] = s_da[h][j];
    }

    float am[3][NP], as[3][NP], av[3][NP];
    #pragma unroll
    for (int h = 0; h < 3; h++)
        #pragma unroll
        for (int j = 0; j < NP; j++) { am[h][j] = -1e30f; as[h][j] = 0.f; av[h][j] = 0.f; }

    const float4* p0 = (const float4*)(x + (size_t)b * 3 * NPIX);
    const float4* p1 = p0 + NPIX/4;
    const float4* p2 = p0 + NPIX/2;
    const int g0 = blk*THR_G + t;

    #pragma unroll 2
    for (int it = 0; it < ITERS_G; it++) {
        int g = g0 + it*(BPB_G*THR_G);
        float4 r0 = p0[g], r1 = p1[g], r2 = p2[g];
        float c0[4] = {r0.x, r0.y, r0.z, r0.w};
        float c1[4] = {r1.x, r1.y, r1.z, r1.w};
        float c2[4] = {r2.x, r2.y, r2.z, r2.w};
        #pragma unroll
        for (int e = 0; e < 4; e++) {
            float x0 = c0[e], x1 = c1[e], x2 = c2[e];
            float mu  = (x0 + x1 + x2) * (1.0f/3.0f);
            float d0 = x0 - mu, d1 = x1 - mu, d2 = x2 - mu;
            float var = (d0*d0 + d1*d1 + d2*d2) * (1.0f/3.0f);
            float inv = rsqrtf(var + EPS);
            float kh[3], vh[3];
            #pragma unroll
            for (int h = 0; h < 3; h++) {
                kh[h] = fmaf(inv, d0*Ak[h][0] + d1*Ak[h][1] + d2*Ak[h][2], Bk[h]);
                vh[h] = fmaf(inv, d0*Av[h][0] + d1*Av[h][1] + d2*Av[h][2], Bv[h]);
            }
            #pragma unroll
            for (int h = 0; h < 3; h++) {
                #pragma unroll
                for (int j = 0; j < NP; j++) {
                    if (j >= cnt[h]) break;
                    float l = da[h][j] * kh[h];
                    if (l > am[h][j]) {
                        float cc = __expf(am[h][j] - l);
                        as[h][j] = fmaf(as[h][j], cc, 1.0f);
                        av[h][j] = fmaf(av[h][j], cc, vh[h]);
                        am[h][j] = l;
                    } else {
                        float e2 = __expf(l - am[h][j]);
                        as[h][j] += e2;
                        av[h][j] = fmaf(e2, vh[h], av[h][j]);
                    }
                }
            }
        }
    }

    #pragma unroll
    for (int h = 0; h < 3; h++) {
        #pragma unroll
        for (int j = 0; j < NP; j++) {
            float m = am[h][j];
            float M = m;
            #pragma unroll
            for (int off = 16; off > 0; off >>= 1)
                M = fmaxf(M, __shfl_xor_sync(0xffffffffu, M, off));
            float f  = __expf(m - M);
            float s  = as[h][j] * f;
            float sv = av[h][j] * f;
            #pragma unroll
            for (int off = 16; off > 0; off >>= 1) {
                s  += __shfl_xor_sync(0xffffffffu, s,  off);
                sv += __shfl_xor_sync(0xffffffffu, sv, off);
            }
            if (lane == 0) {
                s_red[warp][h*NP+j][0] = M;
                s_red[warp][h*NP+j][1] = s;
                s_red[warp][h*NP+j][2] = sv;
            }
        }
    }
    __syncthreads();
    if (t < NSLOT) {
        float M = -1e30f;
        #pragma unroll
        for (int w = 0; w < 4; w++) M = fmaxf(M, s_red[w][t][0]);
        float s = 0.f, sv = 0.f;
        #pragma unroll
        for (int w = 0; w < 4; w++) {
            float f = __expf(s_red[w][t][0] - M);
            s  = fmaf(s_red[w][t][1], f, s);
            sv = fmaf(s_red[w][t][2], f, sv);
        }
        g_part[b][blk][t][0] = M;
        g_part[b][blk][t][1] = s;
        g_part[b][blk][t][2] = sv;
    }
}

// ---------------------------------------------------------------------------
// Kernel 3 (TAIL): one block — combine partials (fast or generic), then
// epilogue (Wp -> LN2 -> SiLU FFN -> residual -> gamma/color).
// ---------------------------------------------------------------------------
__global__ void __launch_bounds__(1024) k_tail(
    const float* __restrict__ qp,
    const float* __restrict__ Wp, const float* __restrict__ bp,
    const float* __restrict__ ln2w, const float* __restrict__ ln2b,
    const float* __restrict__ W1, const float* __restrict__ b1,
    const float* __restrict__ W2, const float* __restrict__ b2,
    const float* __restrict__ Wg, const float* __restrict__ bg,
    const float* __restrict__ Wc, const float* __restrict__ bc,
    const float* __restrict__ gb, const float* __restrict__ cb,
    float* __restrict__ out)
{
    const int t = threadIdx.x;
    const int lane = t & 31;
    const int w = t >> 5;      // 32 warps

    if (g_flag) {
        // fast combine: 48 tasks = 16 batches x 3 heads, each sums 64x4 floats
        for (int task = w; task < NB*3; task += 32) {
            int b = task / 3, h = task % 3;
            float acc[4];
            #pragma unroll
            for (int f = 0; f < 4; f++)
                acc[f] = g_fast[b][lane][h*4+f] + g_fast[b][lane+32][h*4+f];
            #pragma unroll
            for (int f = 0; f < 4; f++) {
                #pragma unroll
                for (int off = 16; off > 0; off >>= 1)
                    acc[f] += __shfl_xor_sync(0xffffffffu, acc[f], off);
            }
            if (lane == 0) {
                float S = acc[0];
                float SV = c_Bv[h]*S + c_Av[h][0]*acc[1] + c_Av[h][1]*acc[2] + c_Av[h][2]*acc[3];
                g_comb[b][h*NP][0] = S;
                g_comb[b][h*NP][1] = SV;
            }
        }
    } else {
        // generic combine: 480 tasks, merge 64 {m,s,sv} partials per task
        for (int task = w; task < NB*NSLOT; task += 32) {
            int b = task / NSLOT, slot = task % NSLOT;
            float m1 = g_part[b][lane][slot][0];
            float s1 = g_part[b][lane][slot][1];
            float v1 = g_part[b][lane][slot][2];
            float m2 = g_part[b][lane+32][slot][0];
            float s2 = g_part[b][lane+32][slot][1];
            float v2 = g_part[b][lane+32][slot][2];
            float m = fmaxf(m1, m2);
            float f1 = __expf(m1 - m), f2 = __expf(m2 - m);
            float s  = s1*f1 + s2*f2;
            float sv = v1*f1 + v2*f2;
            float M = m;
            #pragma unroll
            for (int off = 16; off > 0; off >>= 1)
                M = fmaxf(M, __shfl_xor_sync(0xffffffffu, M, off));
            float f = __expf(m - M);
            s *= f; sv *= f;
            #pragma unroll
            for (int off = 16; off > 0; off >>= 1) {
                s  += __shfl_xor_sync(0xffffffffu, s,  off);
                sv += __shfl_xor_sync(0xffffffffu, sv, off);
            }
            if (lane == 0) {
                g_comb[b][slot][0] = s;
                g_comb[b][slot][1] = sv;
            }
        }
    }
    __syncthreads();

    // epilogue: 160 threads, one per (batch, param)
    if (t >= NB*NP) return;
    int b = t / NP, qi = t % NP;

    float o[3];
    #pragma unroll
    for (int h = 0; h < 3; h++) {
        float list[NP]; int cnt2 = 0; int idx = 0;
        for (int j = 0; j <= qi; j++) {
            float v2 = qp[j*3 + h];
            int f = -1;
            for (int c = 0; c < cnt2; c++) if (list[c] == v2) { f = c; break; }
            if (f < 0) { list[cnt2] = v2; f = cnt2; cnt2++; }
            if (j == qi) idx = f;
        }
        float s  = g_comb[b][h*NP + idx][0];
        float sv = g_comb[b][h*NP + idx][1];
        o[h] = sv / s;
    }

    float op[3];
    #pragma unroll
    for (int e = 0; e < 3; e++)
        op[e] = bp[e] + o[0]*Wp[e*3+0] + o[1]*Wp[e*3+1] + o[2]*Wp[e*3+2];

    float mu = (op[0] + op[1] + op[2]) * (1.0f/3.0f);
    float d0 = op[0]-mu, d1 = op[1]-mu, d2 = op[2]-mu;
    float var = (d0*d0 + d1*d1 + d2*d2) * (1.0f/3.0f);
    float inv = rsqrtf(var + EPS);
    float h2[3];
    h2[0] = d0*inv*ln2w[0] + ln2b[0];
    h2[1] = d1*inv*ln2w[1] + ln2b[1];
    h2[2] = d2*inv*ln2w[2] + ln2b[2];

    float y[3] = { op[0] + b2[0], op[1] + b2[1], op[2] + b2[2] };
    #pragma unroll
    for (int f = 0; f < 12; f++) {
        float u = b1[f] + h2[0]*W1[f*3+0] + h2[1]*W1[f*3+1] + h2[2]*W1[f*3+2];
        float su = u / (1.0f + __expf(-u));
        y[0] += su * W2[0*12 + f];
        y[1] += su * W2[1*12 + f];
        y[2] += su * W2[2*12 + f];
    }

    if (qi == 0) {
        out[b] = bg[0] + gb[0] + y[0]*Wg[0] + y[1]*Wg[1] + y[2]*Wg[2];
    } else {
        int p = qi - 1;
        out[NB + b*9 + p] = bc[0] + y[0]*Wc[0] + y[1]*Wc[1] + y[2]*Wc[2] + cb[p];
    }
}

extern "C" void kernel_launch(void* const* d_in, const int* in_sizes, int n_in,
                              void* d_out, int out_size)
{
    const float* x    = (const float*)d_in[0];
    const float* qp   = (const float*)d_in[1];
    const float* ln1w = (const float*)d_in[2];
    const float* ln1b = (const float*)d_in[3];
    const float* Wk   = (const float*)d_in[4];
    const float* bk   = (const float*)d_in[5];
    const float* Wv   = (const float*)d_in[6];
    const float* bv   = (const float*)d_in[7];
    const float* Wp   = (const float*)d_in[8];
    const float* bp   = (const float*)d_in[9];
    const float* ln2w = (const float*)d_in[10];
    const float* ln2b = (const float*)d_in[11];
    const float* W1   = (const float*)d_in[12];
    const float* b1   = (const float*)d_in[13];
    const float* W2   = (const float*)d_in[14];
    const float* b2   = (const float*)d_in[15];
    const float* Wg   = (const float*)d_in[16];
    const float* bg   = (const float*)d_in[17];
    const float* Wc   = (const float*)d_in[18];
    const float* bc   = (const float*)d_in[19];
    const float* gb   = (const float*)d_in[20];
    const float* cb   = (const float*)d_in[21];
    float* out = (float*)d_out;

    k_init<<<1, 1>>>(qp, ln1w, ln1b, Wk, bk, Wv, bv);
    k_fast<<<NB*BPB, THREADS>>>(x);
    k_generic<<<NB*BPB_G, THR_G>>>(x, qp, ln1w, ln1b, Wk, bk, Wv, bv);
    k_tail<<<1, 1024>>>(qp, Wp, bp, ln2w, ln2b, W1, b1, W2, b2,
                        Wg, bg, Wc, bc, gb, cb, out);
}

// round 3
// speedup vs baseline: 2.3942x; 1.1731x over previous
#include <cuda_runtime.h>
#include <math.h>

#define NB 16
#define NPIX (512*512)
#define NP 10
#define NSLOT 30
#define EPS 1e-5f
#define LOG2E 1.4426950408889634f

// fast kernel geometry: 512 blocks total -> single wave at occupancy 4
#define BPB 32
#define THREADS 256
#define STRIDE (BPB*THREADS)            // 8192 float4-groups per step
#define ITERS ((NPIX/4)/STRIDE)         // 8

// generic fallback geometry
#define BPB_G 64
#define THR_G 128
#define ITERS_G ((NPIX/4)/(BPB_G*THR_G))

// ---- scratch (graph-capture safe device globals) ----
__device__ float g_fast[NB][BPB][12];          // per-block {S,T0,T1,T2} x 3 heads
__device__ int   g_cnt[NB];                    // last-block tickets (self-resetting)
__device__ float g_part[NB][BPB_G][NSLOT][3];  // generic partials {m,s,sv}
__device__ float g_comb[NB][NSLOT][2];

// ---------------------------------------------------------------------------
// Deterministic fast-path test + folded K coefficients (computed redundantly
// by every block/kernel from the same inputs -> bit-identical decision).
// arg(in log2 units) = G[h][0]*u0 + G[h][1]*u1 + C[h],  u2 = -(u0+u1)
// ---------------------------------------------------------------------------
__device__ __forceinline__ int fast_coeffs(
    const float* __restrict__ qp, const float* __restrict__ ln1w,
    const float* __restrict__ ln1b, const float* __restrict__ Wk,
    const float* __restrict__ bk, float G[3][2], float C[3])
{
    int ok = 1;
    #pragma unroll
    for (int h = 0; h < 3; h++) {
        float q = qp[h];
        #pragma unroll
        for (int j = 1; j < NP; j++) ok &= (qp[j*3 + h] == q);
        float F[3]; float n2 = 0.f;
        #pragma unroll
        for (int c = 0; c < 3; c++) {
            F[c] = q * Wk[h*3+c] * ln1w[c];
            n2 += F[c] * F[c];
        }
        float r = 1.7320509f * sqrtf(n2);   // bound: |F.u| <= sqrt3*||F||, ||u||<sqrt3
        ok &= (2.f * r <= 60.f);            // exp range safe with fixed max-shift
        G[h][0] = (F[0] - F[2]) * LOG2E;
        G[h][1] = (F[1] - F[2]) * LOG2E;
        C[h]    = -r * LOG2E;               // arg = (F.u - r) * log2e  in [-2r*log2e, 0]
    }
    return ok;
}

__device__ __forceinline__ float ex2f(float a) {
    float r;
    asm("ex2.approx.f32 %0, %1;" : "=f"(r) : "f"(a));
    return r;
}

// ---------------------------------------------------------------------------
// FAST kernel: stream x once, accumulate {S, T0, T1} per head; last block of
// each batch combines partials and emits that batch's 10 outputs directly.
// ---------------------------------------------------------------------------
__global__ void __launch_bounds__(THREADS, 4) k_fast(
    const float* __restrict__ x,  const float* __restrict__ qp,
    const float* __restrict__ ln1w, const float* __restrict__ ln1b,
    const float* __restrict__ Wk, const float* __restrict__ bk,
    const float* __restrict__ Wv, const float* __restrict__ bv,
    const float* __restrict__ Wp, const float* __restrict__ bp,
    const float* __restrict__ ln2w, const float* __restrict__ ln2b,
    const float* __restrict__ W1, const float* __restrict__ b1,
    const float* __restrict__ W2, const float* __restrict__ b2,
    const float* __restrict__ Wg, const float* __restrict__ bg,
    const float* __restrict__ Wc, const float* __restrict__ bc,
    const float* __restrict__ gb, const float* __restrict__ cb,
    float* __restrict__ out)
{
    float G[3][2], C[3];
    if (!fast_coeffs(qp, ln1w, ln1b, Wk, bk, G, C)) return;

    __shared__ float s_red[THREADS/32][12];
    __shared__ float s_o[3];
    __shared__ int   s_win;

    const int b    = blockIdx.x / BPB;
    const int blk  = blockIdx.x % BPB;
    const int t    = threadIdx.x;
    const int lane = t & 31;
    const int warp = t >> 5;

    float S[3]  = {0.f, 0.f, 0.f};
    float T0[3] = {0.f, 0.f, 0.f};
    float T1[3] = {0.f, 0.f, 0.f};

    const float4* p0 = (const float4*)(x + (size_t)b * 3 * NPIX);
    const float4* p1 = p0 + NPIX/4;
    const float4* p2 = p0 + NPIX/2;

    int g = blk * THREADS + t;
    float4 a0 = __ldcs(p0 + g), a1 = __ldcs(p1 + g), a2 = __ldcs(p2 + g);

    #pragma unroll
    for (int it = 0; it < ITERS; it++) {
        float4 n0, n1, n2;
        if (it + 1 < ITERS) {
            int gn = g + STRIDE;
            n0 = __ldcs(p0 + gn); n1 = __ldcs(p1 + gn); n2 = __ldcs(p2 + gn);
        }
        float c0[4] = {a0.x, a0.y, a0.z, a0.w};
        float c1[4] = {a1.x, a1.y, a1.z, a1.w};
        float c2[4] = {a2.x, a2.y, a2.z, a2.w};
        #pragma unroll
        for (int e = 0; e < 4; e++) {
            float x0 = c0[e], x1 = c1[e], x2 = c2[e];
            float mu = (x0 + x1 + x2) * (1.0f/3.0f);
            float d0 = x0 - mu, d1 = x1 - mu, d2 = x2 - mu;
            float sq = fmaf(d2, d2, fmaf(d1, d1, d0*d0));
            float inv = rsqrtf(fmaf(sq, (1.0f/3.0f), EPS));
            float u0 = d0 * inv, u1 = d1 * inv;
            #pragma unroll
            for (int h = 0; h < 3; h++) {
                float arg = fmaf(u1, G[h][1], fmaf(u0, G[h][0], C[h]));
                float ee  = ex2f(arg);
                S[h]  += ee;
                T0[h]  = fmaf(ee, u0, T0[h]);
                T1[h]  = fmaf(ee, u1, T1[h]);
            }
        }
        a0 = n0; a1 = n1; a2 = n2;
        g += STRIDE;
    }

    // block reduce 12 fields (T2 = -(T0+T1))
    float acc[12];
    #pragma unroll
    for (int h = 0; h < 3; h++) {
        acc[h*4+0] = S[h];
        acc[h*4+1] = T0[h];
        acc[h*4+2] = T1[h];
        acc[h*4+3] = -(T0[h] + T1[h]);
    }
    #pragma unroll
    for (int f = 0; f < 12; f++) {
        float v = acc[f];
        #pragma unroll
        for (int off = 16; off > 0; off >>= 1)
            v += __shfl_xor_sync(0xffffffffu, v, off);
        acc[f] = v;
    }
    if (lane == 0) {
        #pragma unroll
        for (int f = 0; f < 12; f++) s_red[warp][f] = acc[f];
    }
    __syncthreads();
    if (t < 12) {
        float v = 0.f;
        #pragma unroll
        for (int w = 0; w < THREADS/32; w++) v += s_red[w][t];
        g_fast[b][blk][t] = v;
    }
    __threadfence();
    if (t == 0) s_win = (atomicAdd(&g_cnt[b], 1) == BPB - 1);
    __syncthreads();
    if (!s_win) return;

    // ---- winner block: combine 32 partials, compute o[h] = SV/S ----
    if (warp < 3) {
        float4 p = __ldcg((const float4*)&g_fast[b][lane][warp*4]);
        float r0 = p.x, r1 = p.y, r2 = p.z, r3 = p.w;
        #pragma unroll
        for (int off = 16; off > 0; off >>= 1) {
            r0 += __shfl_xor_sync(0xffffffffu, r0, off);
            r1 += __shfl_xor_sync(0xffffffffu, r1, off);
            r2 += __shfl_xor_sync(0xffffffffu, r2, off);
            r3 += __shfl_xor_sync(0xffffffffu, r3, off);
        }
        if (lane == 0) {
            int h = warp;
            float Bvh = bv[h];
            float Av0 = Wv[h*3+0] * ln1w[0];
            float Av1 = Wv[h*3+1] * ln1w[1];
            float Av2 = Wv[h*3+2] * ln1w[2];
            #pragma unroll
            for (int c = 0; c < 3; c++) Bvh += Wv[h*3+c] * ln1b[c];
            float SV = Bvh*r0 + Av0*r1 + Av1*r2 + Av2*r3;
            s_o[h] = SV / r0;
        }
    }
    __syncthreads();
    if (t == 0) {
        g_cnt[b] = 0;   // self-reset for next graph replay

        float o0 = s_o[0], o1 = s_o[1], o2 = s_o[2];
        float op[3];
        #pragma unroll
        for (int e = 0; e < 3; e++)
            op[e] = bp[e] + o0*Wp[e*3+0] + o1*Wp[e*3+1] + o2*Wp[e*3+2];

        float mu = (op[0] + op[1] + op[2]) * (1.0f/3.0f);
        float d0 = op[0]-mu, d1 = op[1]-mu, d2 = op[2]-mu;
        float var = (d0*d0 + d1*d1 + d2*d2) * (1.0f/3.0f);
        float inv = rsqrtf(var + EPS);
        float h2[3];
        h2[0] = d0*inv*ln2w[0] + ln2b[0];
        h2[1] = d1*inv*ln2w[1] + ln2b[1];
        h2[2] = d2*inv*ln2w[2] + ln2b[2];

        float y[3] = { op[0] + b2[0], op[1] + b2[1], op[2] + b2[2] };
        #pragma unroll
        for (int f = 0; f < 12; f++) {
            float u = b1[f] + h2[0]*W1[f*3+0] + h2[1]*W1[f*3+1] + h2[2]*W1[f*3+2];
            float su = u / (1.0f + __expf(-u));
            y[0] += su * W2[0*12 + f];
            y[1] += su * W2[1*12 + f];
            y[2] += su * W2[2*12 + f];
        }
        // all 10 query rows identical in fast path -> one y serves everything
        out[b] = bg[0] + gb[0] + y[0]*Wg[0] + y[1]*Wg[1] + y[2]*Wg[2];
        float colbase = bc[0] + y[0]*Wc[0] + y[1]*Wc[1] + y[2]*Wc[2];
        #pragma unroll
        for (int p = 0; p < 9; p++)
            out[NB + b*9 + p] = colbase + cb[p];
    }
}

// ---------------------------------------------------------------------------
// GENERIC fallback (exact online-softmax over all 30 slots); early-exits when
// the fast path is valid.
// ---------------------------------------------------------------------------
__global__ void __launch_bounds__(THR_G) k_generic(
    const float* __restrict__ x, const float* __restrict__ qp,
    const float* __restrict__ ln1w, const float* __restrict__ ln1b,
    const float* __restrict__ Wk, const float* __restrict__ bk,
    const float* __restrict__ Wv, const float* __restrict__ bv)
{
    {
        float G[3][2], C[3];
        if (fast_coeffs(qp, ln1w, ln1b, Wk, bk, G, C)) return;
    }

    __shared__ float s_da[3][NP];
    __shared__ int   s_cnt[3];
    __shared__ float s_red[4][NSLOT][3];

    const int b    = blockIdx.x / BPB_G;
    const int blk  = blockIdx.x % BPB_G;
    const int t    = threadIdx.x;
    const int lane = t & 31;
    const int warp = t >> 5;

    if (t == 0) {
        for (int h = 0; h < 3; h++) {
            int cnt = 0;
            for (int j = 0; j < NP; j++) {
                float v = qp[j*3 + h];
                int f = -1;
                for (int c = 0; c < cnt; c++) if (s_da[h][c] == v) { f = c; break; }
                if (f < 0) { s_da[h][cnt] = v; cnt++; }
            }
            for (int j = cnt; j < NP; j++) s_da[h][j] = 0.0f;
            s_cnt[h] = cnt;
        }
    }
    __syncthreads();

    float Ak[3][3], Bk[3], Av[3][3], Bv[3];
    #pragma unroll
    for (int h = 0; h < 3; h++) {
        float sk = bk[h], sv0 = bv[h];
        #pragma unroll
        for (int c = 0; c < 3; c++) {
            float wkv = Wk[h*3+c], wvv = Wv[h*3+c];
            float lw = ln1w[c], lb = ln1b[c];
            Ak[h][c] = wkv * lw;
            Av[h][c] = wvv * lw;
            sk  += wkv * lb;
            sv0 += wvv * lb;
        }
        Bk[h] = sk; Bv[h] = sv0;
    }

    float da[3][NP]; int cnt[3];
    #pragma unroll
    for (int h = 0; h < 3; h++) {
        cnt[h] = s_cnt[h];
        #pragma unroll
        for (int j = 0; j < NP; j++) da[h][j] = s_da[h][j];
    }

    float am[3][NP], as[3][NP], av[3][NP];
    #pragma unroll
    for (int h = 0; h < 3; h++)
        #pragma unroll
        for (int j = 0; j < NP; j++) { am[h][j] = -1e30f; as[h][j] = 0.f; av[h][j] = 0.f; }

    const float4* p0 = (const float4*)(x + (size_t)b * 3 * NPIX);
    const float4* p1 = p0 + NPIX/4;
    const float4* p2 = p0 + NPIX/2;
    const int g0 = blk*THR_G + t;

    #pragma unroll 2
    for (int it = 0; it < ITERS_G; it++) {
        int g = g0 + it*(BPB_G*THR_G);
        float4 r0 = p0[g], r1 = p1[g], r2 = p2[g];
        float c0[4] = {r0.x, r0.y, r0.z, r0.w};
        float c1[4] = {r1.x, r1.y, r1.z, r1.w};
        float c2[4] = {r2.x, r2.y, r2.z, r2.w};
        #pragma unroll
        for (int e = 0; e < 4; e++) {
            float x0 = c0[e], x1 = c1[e], x2 = c2[e];
            float mu  = (x0 + x1 + x2) * (1.0f/3.0f);
            float d0 = x0 - mu, d1 = x1 - mu, d2 = x2 - mu;
            float var = (d0*d0 + d1*d1 + d2*d2) * (1.0f/3.0f);
            float inv = rsqrtf(var + EPS);
            float kh[3], vh[3];
            #pragma unroll
            for (int h = 0; h < 3; h++) {
                kh[h] = fmaf(inv, d0*Ak[h][0] + d1*Ak[h][1] + d2*Ak[h][2], Bk[h]);
                vh[h] = fmaf(inv, d0*Av[h][0] + d1*Av[h][1] + d2*Av[h][2], Bv[h]);
            }
            #pragma unroll
            for (int h = 0; h < 3; h++) {
                #pragma unroll
                for (int j = 0; j < NP; j++) {
                    if (j >= cnt[h]) break;
                    float l = da[h][j] * kh[h];
                    if (l > am[h][j]) {
                        float cc = __expf(am[h][j] - l);
                        as[h][j] = fmaf(as[h][j], cc, 1.0f);
                        av[h][j] = fmaf(av[h][j], cc, vh[h]);
                        am[h][j] = l;
                    } else {
                        float e2 = __expf(l - am[h][j]);
                        as[h][j] += e2;
                        av[h][j] = fmaf(e2, vh[h], av[h][j]);
                    }
                }
            }
        }
    }

    #pragma unroll
    for (int h = 0; h < 3; h++) {
        #pragma unroll
        for (int j = 0; j < NP; j++) {
            float m = am[h][j];
            float M = m;
            #pragma unroll
            for (int off = 16; off > 0; off >>= 1)
                M = fmaxf(M, __shfl_xor_sync(0xffffffffu, M, off));
            float f  = __expf(m - M);
            float s  = as[h][j] * f;
            float sv = av[h][j] * f;
            #pragma unroll
            for (int off = 16; off > 0; off >>= 1) {
                s  += __shfl_xor_sync(0xffffffffu, s,  off);
                sv += __shfl_xor_sync(0xffffffffu, sv, off);
            }
            if (lane == 0) {
                s_red[warp][h*NP+j][0] = M;
                s_red[warp][h*NP+j][1] = s;
                s_red[warp][h*NP+j][2] = sv;
            }
        }
    }
    __syncthreads();
    if (t < NSLOT) {
        float M = -1e30f;
        #pragma unroll
        for (int w = 0; w < 4; w++) M = fmaxf(M, s_red[w][t][0]);
        float s = 0.f, sv = 0.f;
        #pragma unroll
        for (int w = 0; w < 4; w++) {
            float f = __expf(s_red[w][t][0] - M);
            s  = fmaf(s_red[w][t][1], f, s);
            sv = fmaf(s_red[w][t][2], f, sv);
        }
        g_part[b][blk][t][0] = M;
        g_part[b][blk][t][1] = s;
        g_part[b][blk][t][2] = sv;
    }
}

// ---------------------------------------------------------------------------
// Generic-path tail (combine + epilogue). Early-exits when fast path handled it.
// ---------------------------------------------------------------------------
__global__ void __launch_bounds__(1024) k_tail(
    const float* __restrict__ qp,
    const float* __restrict__ ln1w, const float* __restrict__ ln1b,
    const float* __restrict__ Wk, const float* __restrict__ bk,
    const float* __restrict__ Wp, const float* __restrict__ bp,
    const float* __restrict__ ln2w, const float* __restrict__ ln2b,
    const float* __restrict__ W1, const float* __restrict__ b1,
    const float* __restrict__ W2, const float* __restrict__ b2,
    const float* __restrict__ Wg, const float* __restrict__ bg,
    const float* __restrict__ Wc, const float* __restrict__ bc,
    const float* __restrict__ gb, const float* __restrict__ cb,
    float* __restrict__ out)
{
    {
        float G[3][2], C[3];
        if (fast_coeffs(qp, ln1w, ln1b, Wk, bk, G, C)) return;
    }

    const int t = threadIdx.x;
    const int lane = t & 31;
    const int w = t >> 5;

    for (int task = w; task < NB*NSLOT; task += 32) {
        int b = task / NSLOT, slot = task % NSLOT;
        float m1 = g_part[b][lane][slot][0];
        float s1 = g_part[b][lane][slot][1];
        float v1 = g_part[b][lane][slot][2];
        float m2 = g_part[b][lane+32][slot][0];
        float s2 = g_part[b][lane+32][slot][1];
        float v2 = g_part[b][lane+32][slot][2];
        float m = fmaxf(m1, m2);
        float f1 = __expf(m1 - m), f2 = __expf(m2 - m);
        float s  = s1*f1 + s2*f2;
        float sv = v1*f1 + v2*f2;
        float M = m;
        #pragma unroll
        for (int off = 16; off > 0; off >>= 1)
            M = fmaxf(M, __shfl_xor_sync(0xffffffffu, M, off));
        float f = __expf(m - M);
        s *= f; sv *= f;
        #pragma unroll
        for (int off = 16; off > 0; off >>= 1) {
            s  += __shfl_xor_sync(0xffffffffu, s,  off);
            sv += __shfl_xor_sync(0xffffffffu, sv, off);
        }
        if (lane == 0) {
            g_comb[b][slot][0] = s;
            g_comb[b][slot][1] = sv;
        }
    }
    __syncthreads();

    if (t >= NB*NP) return;
    int b = t / NP, qi = t % NP;

    float o[3];
    #pragma unroll
    for (int h = 0; h < 3; h++) {
        float list[NP]; int cnt2 = 0; int idx = 0;
        for (int j = 0; j <= qi; j++) {
            float v2 = qp[j*3 + h];
            int f = -1;
            for (int c = 0; c < cnt2; c++) if (list[c] == v2) { f = c; break; }
            if (f < 0) { list[cnt2] = v2; f = cnt2; cnt2++; }
            if (j == qi) idx = f;
        }
        float s  = g_comb[b][h*NP + idx][0];
        float sv = g_comb[b][h*NP + idx][1];
        o[h] = sv / s;
    }

    float op[3];
    #pragma unroll
    for (int e = 0; e < 3; e++)
        op[e] = bp[e] + o[0]*Wp[e*3+0] + o[1]*Wp[e*3+1] + o[2]*Wp[e*3+2];

    float mu = (op[0] + op[1] + op[2]) * (1.0f/3.0f);
    float d0 = op[0]-mu, d1 = op[1]-mu, d2 = op[2]-mu;
    float var = (d0*d0 + d1*d1 + d2*d2) * (1.0f/3.0f);
    float inv = rsqrtf(var + EPS);
    float h2[3];
    h2[0] = d0*inv*ln2w[0] + ln2b[0];
    h2[1] = d1*inv*ln2w[1] + ln2b[1];
    h2[2] = d2*inv*ln2w[2] + ln2b[2];

    float y[3] = { op[0] + b2[0], op[1] + b2[1], op[2] + b2[2] };
    #pragma unroll
    for (int f = 0; f < 12; f++) {
        float u = b1[f] + h2[0]*W1[f*3+0] + h2[1]*W1[f*3+1] + h2[2]*W1[f*3+2];
        float su = u / (1.0f + __expf(-u));
        y[0] += su * W2[0*12 + f];
        y[1] += su * W2[1*12 + f];
        y[2] += su * W2[2*12 + f];
    }

    if (qi == 0) {
        out[b] = bg[0] + gb[0] + y[0]*Wg[0] + y[1]*Wg[1] + y[2]*Wg[2];
    } else {
        int p = qi - 1;
        out[NB + b*9 + p] = bc[0] + y[0]*Wc[0] + y[1]*Wc[1] + y[2]*Wc[2] + cb[p];
    }
}

extern "C" void kernel_launch(void* const* d_in, const int* in_sizes, int n_in,
                              void* d_out, int out_size)
{
    const float* x    = (const float*)d_in[0];
    const float* qp   = (const float*)d_in[1];
    const float* ln1w = (const float*)d_in[2];
    const float* ln1b = (const float*)d_in[3];
    const float* Wk   = (const float*)d_in[4];
    const float* bk   = (const float*)d_in[5];
    const float* Wv   = (const float*)d_in[6];
    const float* bv   = (const float*)d_in[7];
    const float* Wp   = (const float*)d_in[8];
    const float* bp   = (const float*)d_in[9];
    const float* ln2w = (const float*)d_in[10];
    const float* ln2b = (const float*)d_in[11];
    const float* W1   = (const float*)d_in[12];
    const float* b1   = (const float*)d_in[13];
    const float* W2   = (const float*)d_in[14];
    const float* b2   = (const float*)d_in[15];
    const float* Wg   = (const float*)d_in[16];
    const float* bg   = (const float*)d_in[17];
    const float* Wc   = (const float*)d_in[18];
    const float* bc   = (const float*)d_in[19];
    const float* gb   = (const float*)d_in[20];
    const float* cb   = (const float*)d_in[21];
    float* out = (float*)d_out;

    k_fast<<<NB*BPB, THREADS>>>(x, qp, ln1w, ln1b, Wk, bk, Wv, bv,
                                Wp, bp, ln2w, ln2b, W1, b1, W2, b2,
                                Wg, bg, Wc, bc, gb, cb, out);
    k_generic<<<NB*BPB_G, THR_G>>>(x, qp, ln1w, ln1b, Wk, bk, Wv, bv);
    k_tail<<<1, 1024>>>(qp, ln1w, ln1b, Wk, bk, Wp, bp, ln2w, ln2b,
                        W1, b1, W2, b2, Wg, bg, Wc, bc, gb, cb, out);
}

// round 4
// speedup vs baseline: 2.9050x; 1.2133x over previous
#include <cuda_runtime.h>
#include <math.h>

#define NB 16
#define NPIX (512*512)
#define NP 10
#define NSLOT 30
#define EPS 1e-5f
#define LOG2E 1.4426950408889634f

// fast kernel geometry: 16 batches x 37 blocks = 592 = 148 SMs x 4 -> perfectly
// balanced single wave at 64 regs/thread.
#define BPB 37
#define THREADS 256
#define GPB (NPIX/4)                 // 65536 float4-groups per channel per batch
#define FSTRIDE (BPB*THREADS)        // 9472
#define FITERS 7                     // ceil(65536/9472)

// generic fallback geometry
#define BPB_G 64
#define THR_G 128
#define ITERS_G ((NPIX/4)/(BPB_G*THR_G))

typedef unsigned long long ull;

// ---- scratch (graph-capture safe device globals) ----
__device__ int   g_flag;
__device__ __align__(16) float g_fast[NB][BPB][12];   // {S,T0,T1,T2} x 3 heads
__device__ int   g_cnt[NB];                            // fast tickets (self-reset)
__device__ float g_part[NB][BPB_G][NSLOT][3];          // generic partials
__device__ int   g_cnt2[NB];                           // generic tickets

// ---------------- packed f32x2 helpers ----------------
__device__ __forceinline__ ull PK(float lo, float hi) {
    ull r; asm("mov.b64 %0,{%1,%2};" : "=l"(r) : "f"(lo), "f"(hi)); return r;
}
__device__ __forceinline__ void UPK(float& lo, float& hi, ull v) {
    asm("mov.b64 {%0,%1},%2;" : "=f"(lo), "=f"(hi) : "l"(v));
}
__device__ __forceinline__ ull ADD2(ull a, ull b) {
    ull r; asm("add.rn.f32x2 %0,%1,%2;" : "=l"(r) : "l"(a), "l"(b)); return r;
}
__device__ __forceinline__ ull MUL2(ull a, ull b) {
    ull r; asm("mul.rn.f32x2 %0,%1,%2;" : "=l"(r) : "l"(a), "l"(b)); return r;
}
__device__ __forceinline__ ull FMA2(ull a, ull b, ull c) {
    ull r; asm("fma.rn.f32x2 %0,%1,%2,%3;" : "=l"(r) : "l"(a), "l"(b), "l"(c)); return r;
}
__device__ __forceinline__ float ex2f(float a) {
    float r; asm("ex2.approx.f32 %0, %1;" : "=f"(r) : "f"(a)); return r;
}

// Fast-path test + folded K coefficients (deterministic, recomputed per block).
// arg (log2 units) = g0*u0 + g1*u1  (no shift: SV/S is scale invariant; bound
// 2r<=60 keeps unnormalized sums < 2^62, far from fp32 overflow).
__device__ __forceinline__ int fast_coeffs(
    const float* __restrict__ qp, const float* __restrict__ ln1w,
    const float* __restrict__ ln1b, const float* __restrict__ Wk,
    const float* __restrict__ bk, float g0[3], float g1[3])
{
    int ok = 1;
    #pragma unroll
    for (int h = 0; h < 3; h++) {
        float q = qp[h];
        #pragma unroll
        for (int j = 1; j < NP; j++) ok &= (qp[j*3 + h] == q);
        float F[3]; float n2 = 0.f;
        #pragma unroll
        for (int c = 0; c < 3; c++) {
            F[c] = q * Wk[h*3+c] * ln1w[c];
            n2 += F[c] * F[c];
        }
        float r = 1.7320509f * sqrtf(n2);
        ok &= (2.f * r <= 60.f);
        g0[h] = (F[0] - F[2]) * LOG2E;
        g1[h] = (F[1] - F[2]) * LOG2E;
    }
    return ok;
}

// ---------------------------------------------------------------------------
// FAST kernel: packed-f32x2 streaming pass; last block per batch combines and
// emits that batch's 10 outputs.
// ---------------------------------------------------------------------------
__global__ void __launch_bounds__(THREADS, 4) k_fast(
    const float* __restrict__ x,  const float* __restrict__ qp,
    const float* __restrict__ ln1w, const float* __restrict__ ln1b,
    const float* __restrict__ Wk, const float* __restrict__ bk,
    const float* __restrict__ Wv, const float* __restrict__ bv,
    const float* __restrict__ Wp, const float* __restrict__ bp,
    const float* __restrict__ ln2w, const float* __restrict__ ln2b,
    const float* __restrict__ W1, const float* __restrict__ b1,
    const float* __restrict__ W2, const float* __restrict__ b2,
    const float* __restrict__ Wg, const float* __restrict__ bg,
    const float* __restrict__ Wc, const float* __restrict__ bc,
    const float* __restrict__ gb, const float* __restrict__ cb,
    float* __restrict__ out)
{
    float g0s[3], g1s[3];
    int ok = fast_coeffs(qp, ln1w, ln1b, Wk, bk, g0s, g1s);
    if (blockIdx.x == 0 && threadIdx.x == 0) g_flag = ok;
    if (!ok) return;

    __shared__ float s_red[THREADS/32][12];
    __shared__ float s_o[3];
    __shared__ int   s_win;

    const int b    = blockIdx.x / BPB;
    const int blk  = blockIdx.x - b * BPB;
    const int t    = threadIdx.x;
    const int lane = t & 31;
    const int warp = t >> 5;

    // packed broadcast constants
    ull G0[3], G1[3];
    #pragma unroll
    for (int h = 0; h < 3; h++) { G0[h] = PK(g0s[h], g0s[h]); G1[h] = PK(g1s[h], g1s[h]); }
    const ull nthird2  = PK(-1.0f/3.0f, -1.0f/3.0f);
    const ull twoth2   = PK( 2.0f/3.0f,  2.0f/3.0f);
    const ull eps2     = PK(EPS, EPS);

    ull S[3], T0[3], T1[3];
    #pragma unroll
    for (int h = 0; h < 3; h++) { S[h] = 0ull; T0[h] = 0ull; T1[h] = 0ull; }

    const float4* p0 = (const float4*)(x + (size_t)b * 3 * NPIX);
    const float4* p1 = p0 + GPB;
    const float4* p2 = p0 + 2*GPB;

    int g = blk * THREADS + t;
    #pragma unroll
    for (int it = 0; it < FITERS; it++) {
        if (g < GPB) {
            float4 a0 = __ldcs(p0 + g), a1 = __ldcs(p1 + g), a2 = __ldcs(p2 + g);
            #pragma unroll
            for (int pr = 0; pr < 2; pr++) {
                float xa = pr ? a0.z : a0.x, ya = pr ? a0.w : a0.y;
                float xb = pr ? a1.z : a1.x, yb = pr ? a1.w : a1.y;
                float xc = pr ? a2.z : a2.x, yc = pr ? a2.w : a2.y;
                ull c0 = PK(xa, ya), c1 = PK(xb, yb), c2 = PK(xc, yc);
                ull sm = ADD2(ADD2(c0, c1), c2);
                ull nmu = MUL2(sm, nthird2);
                ull d0 = ADD2(c0, nmu);
                ull d1 = ADD2(c1, nmu);
                // d0^2+d1^2+d2^2 = 2(d0^2 + d0*d1 + d1^2)
                ull qq = MUL2(d0, d0);
                ull tq = FMA2(d1, d1, qq);
                ull t2 = FMA2(d0, d1, tq);
                ull vg = FMA2(t2, twoth2, eps2);
                float vl, vh; UPK(vl, vh, vg);
                ull inv2 = PK(rsqrtf(vl), rsqrtf(vh));
                ull u0 = MUL2(d0, inv2), u1 = MUL2(d1, inv2);
                #pragma unroll
                for (int h = 0; h < 3; h++) {
                    ull arg = FMA2(u1, G1[h], MUL2(u0, G0[h]));
                    float al, ah; UPK(al, ah, arg);
                    ull ee = PK(ex2f(al), ex2f(ah));
                    S[h]  = ADD2(S[h], ee);
                    T0[h] = FMA2(ee, u0, T0[h]);
                    T1[h] = FMA2(ee, u1, T1[h]);
                }
            }
        }
        g += FSTRIDE;
    }

    // unpack + block reduce 12 fields (T2 = -(T0+T1))
    float acc[12];
    #pragma unroll
    for (int h = 0; h < 3; h++) {
        float sl, sh, t0l, t0h, t1l, t1h;
        UPK(sl, sh, S[h]); UPK(t0l, t0h, T0[h]); UPK(t1l, t1h, T1[h]);
        float Sv = sl + sh, T0v = t0l + t0h, T1v = t1l + t1h;
        acc[h*4+0] = Sv;
        acc[h*4+1] = T0v;
        acc[h*4+2] = T1v;
        acc[h*4+3] = -(T0v + T1v);
    }
    #pragma unroll
    for (int f = 0; f < 12; f++) {
        float v = acc[f];
        #pragma unroll
        for (int off = 16; off > 0; off >>= 1)
            v += __shfl_xor_sync(0xffffffffu, v, off);
        acc[f] = v;
    }
    if (lane == 0) {
        #pragma unroll
        for (int f = 0; f < 12; f++) s_red[warp][f] = acc[f];
    }
    __syncthreads();
    if (t < 12) {
        float v = 0.f;
        #pragma unroll
        for (int w = 0; w < THREADS/32; w++) v += s_red[w][t];
        g_fast[b][blk][t] = v;
    }
    __threadfence();
    if (t == 0) s_win = (atomicAdd(&g_cnt[b], 1) == BPB - 1);
    __syncthreads();
    if (!s_win) return;

    // ---- winner: combine 37 partials per head, o[h] = SV/S ----
    if (warp < 3) {
        float r0 = 0.f, r1 = 0.f, r2 = 0.f, r3 = 0.f;
        {
            float4 p = __ldcg((const float4*)&g_fast[b][lane][warp*4]);
            r0 = p.x; r1 = p.y; r2 = p.z; r3 = p.w;
        }
        if (lane + 32 < BPB) {
            float4 p = __ldcg((const float4*)&g_fast[b][lane+32][warp*4]);
            r0 += p.x; r1 += p.y; r2 += p.z; r3 += p.w;
        }
        #pragma unroll
        for (int off = 16; off > 0; off >>= 1) {
            r0 += __shfl_xor_sync(0xffffffffu, r0, off);
            r1 += __shfl_xor_sync(0xffffffffu, r1, off);
            r2 += __shfl_xor_sync(0xffffffffu, r2, off);
            r3 += __shfl_xor_sync(0xffffffffu, r3, off);
        }
        if (lane == 0) {
            int h = warp;
            float Bvh = bv[h];
            float Av0 = Wv[h*3+0] * ln1w[0];
            float Av1 = Wv[h*3+1] * ln1w[1];
            float Av2 = Wv[h*3+2] * ln1w[2];
            #pragma unroll
            for (int c = 0; c < 3; c++) Bvh += Wv[h*3+c] * ln1b[c];
            float SV = Bvh*r0 + Av0*r1 + Av1*r2 + Av2*r3;
            s_o[h] = SV / r0;
        }
    }
    __syncthreads();
    if (t == 0) {
        g_cnt[b] = 0;  // reset for next graph replay

        float o0 = s_o[0], o1 = s_o[1], o2 = s_o[2];
        float op[3];
        #pragma unroll
        for (int e = 0; e < 3; e++)
            op[e] = bp[e] + o0*Wp[e*3+0] + o1*Wp[e*3+1] + o2*Wp[e*3+2];

        float mu = (op[0] + op[1] + op[2]) * (1.0f/3.0f);
        float d0 = op[0]-mu, d1 = op[1]-mu, d2 = op[2]-mu;
        float var = (d0*d0 + d1*d1 + d2*d2) * (1.0f/3.0f);
        float inv = rsqrtf(var + EPS);
        float h2[3];
        h2[0] = d0*inv*ln2w[0] + ln2b[0];
        h2[1] = d1*inv*ln2w[1] + ln2b[1];
        h2[2] = d2*inv*ln2w[2] + ln2b[2];

        float y[3] = { op[0] + b2[0], op[1] + b2[1], op[2] + b2[2] };
        #pragma unroll
        for (int f = 0; f < 12; f++) {
            float u = b1[f] + h2[0]*W1[f*3+0] + h2[1]*W1[f*3+1] + h2[2]*W1[f*3+2];
            float su = u / (1.0f + __expf(-u));
            y[0] += su * W2[0*12 + f];
            y[1] += su * W2[1*12 + f];
            y[2] += su * W2[2*12 + f];
        }
        out[b] = bg[0] + gb[0] + y[0]*Wg[0] + y[1]*Wg[1] + y[2]*Wg[2];
        float colbase = bc[0] + y[0]*Wc[0] + y[1]*Wc[1] + y[2]*Wc[2];
        #pragma unroll
        for (int p = 0; p < 9; p++)
            out[NB + b*9 + p] = colbase + cb[p];
    }
}

// ---------------------------------------------------------------------------
// GENERIC fallback: exact online-softmax over all 30 slots with its own
// last-block combine + epilogue. Early-exits on g_flag (written by k_fast).
// ---------------------------------------------------------------------------
__global__ void __launch_bounds__(THR_G) k_generic(
    const float* __restrict__ x, const float* __restrict__ qp,
    const float* __restrict__ ln1w, const float* __restrict__ ln1b,
    const float* __restrict__ Wk, const float* __restrict__ bk,
    const float* __restrict__ Wv, const float* __restrict__ bv,
    const float* __restrict__ Wp, const float* __restrict__ bp,
    const float* __restrict__ ln2w, const float* __restrict__ ln2b,
    const float* __restrict__ W1, const float* __restrict__ b1,
    const float* __restrict__ W2, const float* __restrict__ b2,
    const float* __restrict__ Wg, const float* __restrict__ bg,
    const float* __restrict__ Wc, const float* __restrict__ bc,
    const float* __restrict__ gb, const float* __restrict__ cb,
    float* __restrict__ out)
{
    if (g_flag) return;

    __shared__ float s_da[3][NP];
    __shared__ int   s_cnt[3];
    __shared__ float s_red[4][NSLOT][3];
    __shared__ float s_comb[NSLOT][2];
    __shared__ int   s_win;

    const int b    = blockIdx.x / BPB_G;
    const int blk  = blockIdx.x - b * BPB_G;
    const int t    = threadIdx.x;
    const int lane = t & 31;
    const int warp = t >> 5;

    if (t == 0) {
        for (int h = 0; h < 3; h++) {
            int cnt = 0;
            for (int j = 0; j < NP; j++) {
                float v = qp[j*3 + h];
                int f = -1;
                for (int c = 0; c < cnt; c++) if (s_da[h][c] == v) { f = c; break; }
                if (f < 0) { s_da[h][cnt] = v; cnt++; }
            }
            for (int j = cnt; j < NP; j++) s_da[h][j] = 0.0f;
            s_cnt[h] = cnt;
        }
    }
    __syncthreads();

    float Ak[3][3], Bk[3], Av[3][3], Bv[3];
    #pragma unroll
    for (int h = 0; h < 3; h++) {
        float sk = bk[h], sv0 = bv[h];
        #pragma unroll
        for (int c = 0; c < 3; c++) {
            float wkv = Wk[h*3+c], wvv = Wv[h*3+c];
            float lw = ln1w[c], lb = ln1b[c];
            Ak[h][c] = wkv * lw;
            Av[h][c] = wvv * lw;
            sk  += wkv * lb;
            sv0 += wvv * lb;
        }
        Bk[h] = sk; Bv[h] = sv0;
    }

    float da[3][NP]; int cnt[3];
    #pragma unroll
    for (int h = 0; h < 3; h++) {
        cnt[h] = s_cnt[h];
        #pragma unroll
        for (int j = 0; j < NP; j++) da[h][j] = s_da[h][j];
    }

    float am[3][NP], as[3][NP], avv[3][NP];
    #pragma unroll
    for (int h = 0; h < 3; h++)
        #pragma unroll
        for (int j = 0; j < NP; j++) { am[h][j] = -1e30f; as[h][j] = 0.f; avv[h][j] = 0.f; }

    const float4* p0 = (const float4*)(x + (size_t)b * 3 * NPIX);
    const float4* p1 = p0 + NPIX/4;
    const float4* p2 = p0 + NPIX/2;
    const int gbase = blk*THR_G + t;

    for (int it = 0; it < ITERS_G; it++) {
        int g = gbase + it*(BPB_G*THR_G);
        float4 r0 = p0[g], r1 = p1[g], r2 = p2[g];
        float c0[4] = {r0.x, r0.y, r0.z, r0.w};
        float c1[4] = {r1.x, r1.y, r1.z, r1.w};
        float c2[4] = {r2.x, r2.y, r2.z, r2.w};
        #pragma unroll
        for (int e = 0; e < 4; e++) {
            float x0 = c0[e], x1 = c1[e], x2 = c2[e];
            float mu  = (x0 + x1 + x2) * (1.0f/3.0f);
            float d0 = x0 - mu, d1 = x1 - mu, d2 = x2 - mu;
            float var = (d0*d0 + d1*d1 + d2*d2) * (1.0f/3.0f);
            float inv = rsqrtf(var + EPS);
            float kh[3], vh[3];
            #pragma unroll
            for (int h = 0; h < 3; h++) {
                kh[h] = fmaf(inv, d0*Ak[h][0] + d1*Ak[h][1] + d2*Ak[h][2], Bk[h]);
                vh[h] = fmaf(inv, d0*Av[h][0] + d1*Av[h][1] + d2*Av[h][2], Bv[h]);
            }
            #pragma unroll
            for (int h = 0; h < 3; h++) {
                #pragma unroll
                for (int j = 0; j < NP; j++) {
                    if (j >= cnt[h]) break;
                    float l = da[h][j] * kh[h];
                    if (l > am[h][j]) {
                        float cc = __expf(am[h][j] - l);
                        as[h][j]  = fmaf(as[h][j], cc, 1.0f);
                        avv[h][j] = fmaf(avv[h][j], cc, vh[h]);
                        am[h][j] = l;
                    } else {
                        float e2 = __expf(l - am[h][j]);
                        as[h][j] += e2;
                        avv[h][j] = fmaf(e2, vh[h], avv[h][j]);
                    }
                }
            }
        }
    }

    #pragma unroll
    for (int h = 0; h < 3; h++) {
        #pragma unroll
        for (int j = 0; j < NP; j++) {
            float m = am[h][j];
            float M = m;
            #pragma unroll
            for (int off = 16; off > 0; off >>= 1)
                M = fmaxf(M, __shfl_xor_sync(0xffffffffu, M, off));
            float f  = __expf(m - M);
            float s  = as[h][j] * f;
            float sv = avv[h][j] * f;
            #pragma unroll
            for (int off = 16; off > 0; off >>= 1) {
                s  += __shfl_xor_sync(0xffffffffu, s,  off);
                sv += __shfl_xor_sync(0xffffffffu, sv, off);
            }
            if (lane == 0) {
                s_red[warp][h*NP+j][0] = M;
                s_red[warp][h*NP+j][1] = s;
                s_red[warp][h*NP+j][2] = sv;
            }
        }
    }
    __syncthreads();
    if (t < NSLOT) {
        float M = -1e30f;
        #pragma unroll
        for (int w = 0; w < 4; w++) M = fmaxf(M, s_red[w][t][0]);
        float s = 0.f, sv = 0.f;
        #pragma unroll
        for (int w = 0; w < 4; w++) {
            float f = __expf(s_red[w][t][0] - M);
            s  = fmaf(s_red[w][t][1], f, s);
            sv = fmaf(s_red[w][t][2], f, sv);
        }
        g_part[b][blk][t][0] = M;
        g_part[b][blk][t][1] = s;
        g_part[b][blk][t][2] = sv;
    }
    __threadfence();
    if (t == 0) s_win = (atomicAdd(&g_cnt2[b], 1) == BPB_G - 1);
    __syncthreads();
    if (!s_win) return;

    // ---- winner: combine 64 partials per slot, then epilogue for batch b ----
    for (int slot = warp; slot < NSLOT; slot += 4) {
        float m1 = g_part[b][lane][slot][0];
        float s1 = g_part[b][lane][slot][1];
        float v1 = g_part[b][lane][slot][2];
        float m2 = g_part[b][lane+32][slot][0];
        float s2 = g_part[b][lane+32][slot][1];
        float v2 = g_part[b][lane+32][slot][2];
        float m = fmaxf(m1, m2);
        float f1 = __expf(m1 - m), f2 = __expf(m2 - m);
        float s  = s1*f1 + s2*f2;
        float sv = v1*f1 + v2*f2;
        float M = m;
        #pragma unroll
        for (int off = 16; off > 0; off >>= 1)
            M = fmaxf(M, __shfl_xor_sync(0xffffffffu, M, off));
        float f = __expf(m - M);
        s *= f; sv *= f;
        #pragma unroll
        for (int off = 16; off > 0; off >>= 1) {
            s  += __shfl_xor_sync(0xffffffffu, s,  off);
            sv += __shfl_xor_sync(0xffffffffu, sv, off);
        }
        if (lane == 0) {
            s_comb[slot][0] = s;
            s_comb[slot][1] = sv;
        }
    }
    __syncthreads();

    if (t == 0) g_cnt2[b] = 0;    // reset for replay
    if (t >= NP) return;
    int qi = t;

    float o[3];
    #pragma unroll
    for (int h = 0; h < 3; h++) {
        float list[NP]; int cnt2 = 0; int idx = 0;
        for (int j = 0; j <= qi; j++) {
            float v2 = qp[j*3 + h];
            int f = -1;
            for (int c = 0; c < cnt2; c++) if (list[c] == v2) { f = c; break; }
            if (f < 0) { list[cnt2] = v2; f = cnt2; cnt2++; }
            if (j == qi) idx = f;
        }
        o[h] = s_comb[h*NP + idx][1] / s_comb[h*NP + idx][0];
    }

    float op[3];
    #pragma unroll
    for (int e = 0; e < 3; e++)
        op[e] = bp[e] + o[0]*Wp[e*3+0] + o[1]*Wp[e*3+1] + o[2]*Wp[e*3+2];

    float mu = (op[0] + op[1] + op[2]) * (1.0f/3.0f);
    float d0 = op[0]-mu, d1 = op[1]-mu, d2 = op[2]-mu;
    float var = (d0*d0 + d1*d1 + d2*d2) * (1.0f/3.0f);
    float inv = rsqrtf(var + EPS);
    float h2[3];
    h2[0] = d0*inv*ln2w[0] + ln2b[0];
    h2[1] = d1*inv*ln2w[1] + ln2b[1];
    h2[2] = d2*inv*ln2w[2] + ln2b[2];

    float y[3] = { op[0] + b2[0], op[1] + b2[1], op[2] + b2[2] };
    #pragma unroll
    for (int f = 0; f < 12; f++) {
        float u = b1[f] + h2[0]*W1[f*3+0] + h2[1]*W1[f*3+1] + h2[2]*W1[f*3+2];
        float su = u / (1.0f + __expf(-u));
        y[0] += su * W2[0*12 + f];
        y[1] += su * W2[1*12 + f];
        y[2] += su * W2[2*12 + f];
    }

    if (qi == 0) {
        out[b] = bg[0] + gb[0] + y[0]*Wg[0] + y[1]*Wg[1] + y[2]*Wg[2];
    } else {
        int p = qi - 1;
        out[NB + b*9 + p] = bc[0] + y[0]*Wc[0] + y[1]*Wc[1] + y[2]*Wc[2] + cb[p];
    }
}

extern "C" void kernel_launch(void* const* d_in, const int* in_sizes, int n_in,
                              void* d_out, int out_size)
{
    const float* x    = (const float*)d_in[0];
    const float* qp   = (const float*)d_in[1];
    const float* ln1w = (const float*)d_in[2];
    const float* ln1b = (const float*)d_in[3];
    const float* Wk   = (const float*)d_in[4];
    const float* bk   = (const float*)d_in[5];
    const float* Wv   = (const float*)d_in[6];
    const float* bv   = (const float*)d_in[7];
    const float* Wp   = (const float*)d_in[8];
    const float* bp   = (const float*)d_in[9];
    const float* ln2w = (const float*)d_in[10];
    const float* ln2b = (const float*)d_in[11];
    const float* W1   = (const float*)d_in[12];
    const float* b1   = (const float*)d_in[13];
    const float* W2   = (const float*)d_in[14];
    const float* b2   = (const float*)d_in[15];
    const float* Wg   = (const float*)d_in[16];
    const float* bg   = (const float*)d_in[17];
    const float* Wc   = (const float*)d_in[18];
    const float* bc   = (const float*)d_in[19];
    const float* gb   = (const float*)d_in[20];
    const float* cb   = (const float*)d_in[21];
    float* out = (float*)d_out;

    k_fast<<<NB*BPB, THREADS>>>(x, qp, ln1w, ln1b, Wk, bk, Wv, bv,
                                Wp, bp, ln2w, ln2b, W1, b1, W2, b2,
                                Wg, bg, Wc, bc, gb, cb, out);
    k_generic<<<NB*BPB_G, THR_G>>>(x, qp, ln1w, ln1b, Wk, bk, Wv, bv,
                                   Wp, bp, ln2w, ln2b, W1, b1, W2, b2,
                                   Wg, bg, Wc, bc, gb, cb, out);
}

// round 5
// speedup vs baseline: 2.9443x; 1.0135x over previous
#include <cuda_runtime.h>
#include <math.h>

#define NB 16
#define NPIX (512*512)
#define NP 10
#define NSLOT 30
#define EPS 1e-5f
#define LOG2E 1.4426950408889634f

// fast kernel geometry: 16 x 37 = 592 = 148 SMs x 4 blocks, single wave
#define BPB 37
#define THREADS 256
#define GPB (NPIX/4)
#define FSTRIDE (BPB*THREADS)        // 9472
#define FITERS 7

// generic fallback geometry
#define BPB_G 64
#define THR_G 128
#define ITERS_G ((NPIX/4)/(BPB_G*THR_G))

typedef unsigned long long ull;

// ---- scratch (graph-capture safe device globals) ----
__device__ int   g_flag;
__device__ __align__(16) float g_fast[NB][BPB][12];
__device__ int   g_cnt[NB];
__device__ float g_part[NB][BPB_G][NSLOT][3];
__device__ int   g_cnt2[NB];

// ---------------- packed f32x2 helpers ----------------
__device__ __forceinline__ ull PK(float lo, float hi) {
    ull r; asm("mov.b64 %0,{%1,%2};" : "=l"(r) : "f"(lo), "f"(hi)); return r;
}
__device__ __forceinline__ void UPK(float& lo, float& hi, ull v) {
    asm("mov.b64 {%0,%1},%2;" : "=f"(lo), "=f"(hi) : "l"(v));
}
__device__ __forceinline__ ull ADD2(ull a, ull b) {
    ull r; asm("add.rn.f32x2 %0,%1,%2;" : "=l"(r) : "l"(a), "l"(b)); return r;
}
__device__ __forceinline__ ull MUL2(ull a, ull b) {
    ull r; asm("mul.rn.f32x2 %0,%1,%2;" : "=l"(r) : "l"(a), "l"(b)); return r;
}
__device__ __forceinline__ ull FMA2(ull a, ull b, ull c) {
    ull r; asm("fma.rn.f32x2 %0,%1,%2,%3;" : "=l"(r) : "l"(a), "l"(b), "l"(c)); return r;
}
__device__ __forceinline__ float ex2f(float a) {
    float r; asm("ex2.approx.f32 %0, %1;" : "=f"(r) : "f"(a)); return r;
}

__device__ __forceinline__ int fast_coeffs(
    const float* __restrict__ qp, const float* __restrict__ ln1w,
    const float* __restrict__ ln1b, const float* __restrict__ Wk,
    const float* __restrict__ bk, float g0[3], float g1[3])
{
    int ok = 1;
    #pragma unroll
    for (int h = 0; h < 3; h++) {
        float q = qp[h];
        #pragma unroll
        for (int j = 1; j < NP; j++) ok &= (qp[j*3 + h] == q);
        float F[3]; float n2 = 0.f;
        #pragma unroll
        for (int c = 0; c < 3; c++) {
            F[c] = q * Wk[h*3+c] * ln1w[c];
            n2 += F[c] * F[c];
        }
        float r = 1.7320509f * sqrtf(n2);
        ok &= (2.f * r <= 60.f);
        g0[h] = (F[0] - F[2]) * LOG2E;
        g1[h] = (F[1] - F[2]) * LOG2E;
    }
    return ok;
}

// ---------------------------------------------------------------------------
// FAST kernel: packed f32x2 streaming pass with double-buffered loads;
// last block per batch combines and writes the batch's 10 outputs.
// Publishes g_flag + PDL trigger BEFORE the heavy loop so the fallback
// kernel's early-exit overlaps this kernel.
// ---------------------------------------------------------------------------
__global__ void __launch_bounds__(THREADS, 4) k_fast(
    const float* __restrict__ x,  const float* __restrict__ qp,
    const float* __restrict__ ln1w, const float* __restrict__ ln1b,
    const float* __restrict__ Wk, const float* __restrict__ bk,
    const float* __restrict__ Wv, const float* __restrict__ bv,
    const float* __restrict__ Wp, const float* __restrict__ bp,
    const float* __restrict__ ln2w, const float* __restrict__ ln2b,
    const float* __restrict__ W1, const float* __restrict__ b1,
    const float* __restrict__ W2, const float* __restrict__ b2,
    const float* __restrict__ Wg, const float* __restrict__ bg,
    const float* __restrict__ Wc, const float* __restrict__ bc,
    const float* __restrict__ gb, const float* __restrict__ cb,
    float* __restrict__ out)
{
    float g0s[3], g1s[3];
    int ok = fast_coeffs(qp, ln1w, ln1b, Wk, bk, g0s, g1s);
    if (blockIdx.x == 0 && threadIdx.x == 0) {
        g_flag = ok;
        __threadfence();
    }
    // let the dependent (fallback) kernel launch now
    cudaTriggerProgrammaticLaunchCompletion();
    if (!ok) return;

    __shared__ float s_red[THREADS/32][12];
    __shared__ float s_o[3];
    __shared__ int   s_win;

    const int b    = blockIdx.x / BPB;
    const int blk  = blockIdx.x - b * BPB;
    const int t    = threadIdx.x;
    const int lane = t & 31;
    const int warp = t >> 5;

    ull G0[3], G1[3];
    #pragma unroll
    for (int h = 0; h < 3; h++) { G0[h] = PK(g0s[h], g0s[h]); G1[h] = PK(g1s[h], g1s[h]); }
    const ull nthird2 = PK(-1.0f/3.0f, -1.0f/3.0f);
    const ull twoth2  = PK( 2.0f/3.0f,  2.0f/3.0f);
    const ull eps2    = PK(EPS, EPS);

    ull S[3], T0[3], T1[3];
    #pragma unroll
    for (int h = 0; h < 3; h++) { S[h] = 0ull; T0[h] = 0ull; T1[h] = 0ull; }

    const float4* p0 = (const float4*)(x + (size_t)b * 3 * NPIX);
    const float4* p1 = p0 + GPB;
    const float4* p2 = p0 + 2*GPB;

    int g = blk * THREADS + t;
    bool v = (g < GPB);
    float4 a0, a1, a2;
    if (v) { a0 = __ldcs(p0 + g); a1 = __ldcs(p1 + g); a2 = __ldcs(p2 + g); }

    #pragma unroll
    for (int it = 0; it < FITERS; it++) {
        int gn = g + FSTRIDE;
        bool vn = (it + 1 < FITERS) && (gn < GPB);
        float4 n0, n1, n2;
        if (vn) { n0 = __ldcs(p0 + gn); n1 = __ldcs(p1 + gn); n2 = __ldcs(p2 + gn); }
        if (v) {
            #pragma unroll
            for (int pr = 0; pr < 2; pr++) {
                float xa = pr ? a0.z : a0.x, ya = pr ? a0.w : a0.y;
                float xb = pr ? a1.z : a1.x, yb = pr ? a1.w : a1.y;
                float xc = pr ? a2.z : a2.x, yc = pr ? a2.w : a2.y;
                ull c0 = PK(xa, ya), c1 = PK(xb, yb), c2 = PK(xc, yc);
                ull sm = ADD2(ADD2(c0, c1), c2);
                ull nmu = MUL2(sm, nthird2);
                ull d0 = ADD2(c0, nmu);
                ull d1 = ADD2(c1, nmu);
                ull qq = MUL2(d0, d0);
                ull tq = FMA2(d1, d1, qq);
                ull t2 = FMA2(d0, d1, tq);
                ull vg = FMA2(t2, twoth2, eps2);
                float vl, vh; UPK(vl, vh, vg);
                ull inv2 = PK(rsqrtf(vl), rsqrtf(vh));
                ull u0 = MUL2(d0, inv2), u1 = MUL2(d1, inv2);
                #pragma unroll
                for (int h = 0; h < 3; h++) {
                    ull arg = FMA2(u1, G1[h], MUL2(u0, G0[h]));
                    float al, ah; UPK(al, ah, arg);
                    ull ee = PK(ex2f(al), ex2f(ah));
                    S[h]  = ADD2(S[h], ee);
                    T0[h] = FMA2(ee, u0, T0[h]);
                    T1[h] = FMA2(ee, u1, T1[h]);
                }
            }
        }
        a0 = n0; a1 = n1; a2 = n2;
        g = gn; v = vn;
    }

    float acc[12];
    #pragma unroll
    for (int h = 0; h < 3; h++) {
        float sl, sh, t0l, t0h, t1l, t1h;
        UPK(sl, sh, S[h]); UPK(t0l, t0h, T0[h]); UPK(t1l, t1h, T1[h]);
        float Sv = sl + sh, T0v = t0l + t0h, T1v = t1l + t1h;
        acc[h*4+0] = Sv;
        acc[h*4+1] = T0v;
        acc[h*4+2] = T1v;
        acc[h*4+3] = -(T0v + T1v);
    }
    #pragma unroll
    for (int f = 0; f < 12; f++) {
        float vv = acc[f];
        #pragma unroll
        for (int off = 16; off > 0; off >>= 1)
            vv += __shfl_xor_sync(0xffffffffu, vv, off);
        acc[f] = vv;
    }
    if (lane == 0) {
        #pragma unroll
        for (int f = 0; f < 12; f++) s_red[warp][f] = acc[f];
    }
    __syncthreads();
    if (t < 12) {
        float vv = 0.f;
        #pragma unroll
        for (int w = 0; w < THREADS/32; w++) vv += s_red[w][t];
        g_fast[b][blk][t] = vv;
    }
    __threadfence();
    if (t == 0) s_win = (atomicAdd(&g_cnt[b], 1) == BPB - 1);
    __syncthreads();
    if (!s_win) return;

    if (warp < 3) {
        float r0 = 0.f, r1 = 0.f, r2 = 0.f, r3 = 0.f;
        {
            float4 p = __ldcg((const float4*)&g_fast[b][lane][warp*4]);
            r0 = p.x; r1 = p.y; r2 = p.z; r3 = p.w;
        }
        if (lane + 32 < BPB) {
            float4 p = __ldcg((const float4*)&g_fast[b][lane+32][warp*4]);
            r0 += p.x; r1 += p.y; r2 += p.z; r3 += p.w;
        }
        #pragma unroll
        for (int off = 16; off > 0; off >>= 1) {
            r0 += __shfl_xor_sync(0xffffffffu, r0, off);
            r1 += __shfl_xor_sync(0xffffffffu, r1, off);
            r2 += __shfl_xor_sync(0xffffffffu, r2, off);
            r3 += __shfl_xor_sync(0xffffffffu, r3, off);
        }
        if (lane == 0) {
            int h = warp;
            float Bvh = bv[h];
            float Av0 = Wv[h*3+0] * ln1w[0];
            float Av1 = Wv[h*3+1] * ln1w[1];
            float Av2 = Wv[h*3+2] * ln1w[2];
            #pragma unroll
            for (int c = 0; c < 3; c++) Bvh += Wv[h*3+c] * ln1b[c];
            float SV = Bvh*r0 + Av0*r1 + Av1*r2 + Av2*r3;
            s_o[h] = SV / r0;
        }
    }
    __syncthreads();
    if (t == 0) {
        g_cnt[b] = 0;

        float o0 = s_o[0], o1 = s_o[1], o2 = s_o[2];
        float op[3];
        #pragma unroll
        for (int e = 0; e < 3; e++)
            op[e] = bp[e] + o0*Wp[e*3+0] + o1*Wp[e*3+1] + o2*Wp[e*3+2];

        float mu = (op[0] + op[1] + op[2]) * (1.0f/3.0f);
        float d0 = op[0]-mu, d1 = op[1]-mu, d2 = op[2]-mu;
        float var = (d0*d0 + d1*d1 + d2*d2) * (1.0f/3.0f);
        float inv = rsqrtf(var + EPS);
        float h2[3];
        h2[0] = d0*inv*ln2w[0] + ln2b[0];
        h2[1] = d1*inv*ln2w[1] + ln2b[1];
        h2[2] = d2*inv*ln2w[2] + ln2b[2];

        float y[3] = { op[0] + b2[0], op[1] + b2[1], op[2] + b2[2] };
        #pragma unroll
        for (int f = 0; f < 12; f++) {
            float u = b1[f] + h2[0]*W1[f*3+0] + h2[1]*W1[f*3+1] + h2[2]*W1[f*3+2];
            float su = u / (1.0f + __expf(-u));
            y[0] += su * W2[0*12 + f];
            y[1] += su * W2[1*12 + f];
            y[2] += su * W2[2*12 + f];
        }
        out[b] = bg[0] + gb[0] + y[0]*Wg[0] + y[1]*Wg[1] + y[2]*Wg[2];
        float colbase = bc[0] + y[0]*Wc[0] + y[1]*Wc[1] + y[2]*Wc[2];
        #pragma unroll
        for (int p = 0; p < 9; p++)
            out[NB + b*9 + p] = colbase + cb[p];
    }
}

// ---------------------------------------------------------------------------
// GENERIC fallback (PDL-overlapped): waits on the upstream grid, reads g_flag,
// exits in the fast case; otherwise full exact online-softmax + epilogue.
// ---------------------------------------------------------------------------
__global__ void __launch_bounds__(THR_G) k_generic(
    const float* __restrict__ x, const float* __restrict__ qp,
    const float* __restrict__ ln1w, const float* __restrict__ ln1b,
    const float* __restrict__ Wk, const float* __restrict__ bk,
    const float* __restrict__ Wv, const float* __restrict__ bv,
    const float* __restrict__ Wp, const float* __restrict__ bp,
    const float* __restrict__ ln2w, const float* __restrict__ ln2b,
    const float* __restrict__ W1, const float* __restrict__ b1,
    const float* __restrict__ W2, const float* __restrict__ b2,
    const float* __restrict__ Wg, const float* __restrict__ bg,
    const float* __restrict__ Wc, const float* __restrict__ bc,
    const float* __restrict__ gb, const float* __restrict__ cb,
    float* __restrict__ out)
{
    cudaGridDependencySynchronize();
    if (*(volatile int*)&g_flag) return;

    __shared__ float s_da[3][NP];
    __shared__ int   s_cnt[3];
    __shared__ float s_red[4][NSLOT][3];
    __shared__ float s_comb[NSLOT][2];
    __shared__ int   s_win;

    const int b    = blockIdx.x / BPB_G;
    const int blk  = blockIdx.x - b * BPB_G;
    const int t    = threadIdx.x;
    const int lane = t & 31;
    const int warp = t >> 5;

    if (t == 0) {
        for (int h = 0; h < 3; h++) {
            int cnt = 0;
            for (int j = 0; j < NP; j++) {
                float v = qp[j*3 + h];
                int f = -1;
                for (int c = 0; c < cnt; c++) if (s_da[h][c] == v) { f = c; break; }
                if (f < 0) { s_da[h][cnt] = v; cnt++; }
            }
            for (int j = cnt; j < NP; j++) s_da[h][j] = 0.0f;
            s_cnt[h] = cnt;
        }
    }
    __syncthreads();

    float Ak[3][3], Bk[3], Av[3][3], Bv[3];
    #pragma unroll
    for (int h = 0; h < 3; h++) {
        float sk = bk[h], sv0 = bv[h];
        #pragma unroll
        for (int c = 0; c < 3; c++) {
            float wkv = Wk[h*3+c], wvv = Wv[h*3+c];
            float lw = ln1w[c], lb = ln1b[c];
            Ak[h][c] = wkv * lw;
            Av[h][c] = wvv * lw;
            sk  += wkv * lb;
            sv0 += wvv * lb;
        }
        Bk[h] = sk; Bv[h] = sv0;
    }

    float da[3][NP]; int cnt[3];
    #pragma unroll
    for (int h = 0; h < 3; h++) {
        cnt[h] = s_cnt[h];
        #pragma unroll
        for (int j = 0; j < NP; j++) da[h][j] = s_da[h][j];
    }

    float am[3][NP], as[3][NP], avv[3][NP];
    #pragma unroll
    for (int h = 0; h < 3; h++)
        #pragma unroll
        for (int j = 0; j < NP; j++) { am[h][j] = -1e30f; as[h][j] = 0.f; avv[h][j] = 0.f; }

    const float4* p0 = (const float4*)(x + (size_t)b * 3 * NPIX);
    const float4* p1 = p0 + NPIX/4;
    const float4* p2 = p0 + NPIX/2;
    const int gbase = blk*THR_G + t;

    for (int it = 0; it < ITERS_G; it++) {
        int g = gbase + it*(BPB_G*THR_G);
        float4 r0 = p0[g], r1 = p1[g], r2 = p2[g];
        float c0[4] = {r0.x, r0.y, r0.z, r0.w};
        float c1[4] = {r1.x, r1.y, r1.z, r1.w};
        float c2[4] = {r2.x, r2.y, r2.z, r2.w};
        #pragma unroll
        for (int e = 0; e < 4; e++) {
            float x0 = c0[e], x1 = c1[e], x2 = c2[e];
            float mu  = (x0 + x1 + x2) * (1.0f/3.0f);
            float d0 = x0 - mu, d1 = x1 - mu, d2 = x2 - mu;
            float var = (d0*d0 + d1*d1 + d2*d2) * (1.0f/3.0f);
            float inv = rsqrtf(var + EPS);
            float kh[3], vh[3];
            #pragma unroll
            for (int h = 0; h < 3; h++) {
                kh[h] = fmaf(inv, d0*Ak[h][0] + d1*Ak[h][1] + d2*Ak[h][2], Bk[h]);
                vh[h] = fmaf(inv, d0*Av[h][0] + d1*Av[h][1] + d2*Av[h][2], Bv[h]);
            }
            #pragma unroll
            for (int h = 0; h < 3; h++) {
                #pragma unroll
                for (int j = 0; j < NP; j++) {
                    if (j >= cnt[h]) break;
                    float l = da[h][j] * kh[h];
                    if (l > am[h][j]) {
                        float cc = __expf(am[h][j] - l);
                        as[h][j]  = fmaf(as[h][j], cc, 1.0f);
                        avv[h][j] = fmaf(avv[h][j], cc, vh[h]);
                        am[h][j] = l;
                    } else {
                        float e2 = __expf(l - am[h][j]);
                        as[h][j] += e2;
                        avv[h][j] = fmaf(e2, vh[h], avv[h][j]);
                    }
                }
            }
        }
    }

    #pragma unroll
    for (int h = 0; h < 3; h++) {
        #pragma unroll
        for (int j = 0; j < NP; j++) {
            float m = am[h][j];
            float M = m;
            #pragma unroll
            for (int off = 16; off > 0; off >>= 1)
                M = fmaxf(M, __shfl_xor_sync(0xffffffffu, M, off));
            float f  = __expf(m - M);
            float s  = as[h][j] * f;
            float sv = avv[h][j] * f;
            #pragma unroll
            for (int off = 16; off > 0; off >>= 1) {
                s  += __shfl_xor_sync(0xffffffffu, s,  off);
                sv += __shfl_xor_sync(0xffffffffu, sv, off);
            }
            if (lane == 0) {
                s_red[warp][h*NP+j][0] = M;
                s_red[warp][h*NP+j][1] = s;
                s_red[warp][h*NP+j][2] = sv;
            }
        }
    }
    __syncthreads();
    if (t < NSLOT) {
        float M = -1e30f;
        #pragma unroll
        for (int w = 0; w < 4; w++) M = fmaxf(M, s_red[w][t][0]);
        float s = 0.f, sv = 0.f;
        #pragma unroll
        for (int w = 0; w < 4; w++) {
            float f = __expf(s_red[w][t][0] - M);
            s  = fmaf(s_red[w][t][1], f, s);
            sv = fmaf(s_red[w][t][2], f, sv);
        }
        g_part[b][blk][t][0] = M;
        g_part[b][blk][t][1] = s;
        g_part[b][blk][t][2] = sv;
    }
    __threadfence();
    if (t == 0) s_win = (atomicAdd(&g_cnt2[b], 1) == BPB_G - 1);
    __syncthreads();
    if (!s_win) return;

    for (int slot = warp; slot < NSLOT; slot += 4) {
        float m1 = g_part[b][lane][slot][0];
        float s1 = g_part[b][lane][slot][1];
        float v1 = g_part[b][lane][slot][2];
        float m2 = g_part[b][lane+32][slot][0];
        float s2 = g_part[b][lane+32][slot][1];
        float v2 = g_part[b][lane+32][slot][2];
        float m = fmaxf(m1, m2);
        float f1 = __expf(m1 - m), f2 = __expf(m2 - m);
        float s  = s1*f1 + s2*f2;
        float sv = v1*f1 + v2*f2;
        float M = m;
        #pragma unroll
        for (int off = 16; off > 0; off >>= 1)
            M = fmaxf(M, __shfl_xor_sync(0xffffffffu, M, off));
        float f = __expf(m - M);
        s *= f; sv *= f;
        #pragma unroll
        for (int off = 16; off > 0; off >>= 1) {
            s  += __shfl_xor_sync(0xffffffffu, s,  off);
            sv += __shfl_xor_sync(0xffffffffu, sv, off);
        }
        if (lane == 0) {
            s_comb[slot][0] = s;
            s_comb[slot][1] = sv;
        }
    }
    __syncthreads();

    if (t == 0) g_cnt2[b] = 0;
    if (t >= NP) return;
    int qi = t;

    float o[3];
    #pragma unroll
    for (int h = 0; h < 3; h++) {
        float list[NP]; int cnt2 = 0; int idx = 0;
        for (int j = 0; j <= qi; j++) {
            float v2 = qp[j*3 + h];
            int f = -1;
            for (int c = 0; c < cnt2; c++) if (list[c] == v2) { f = c; break; }
            if (f < 0) { list[cnt2] = v2; f = cnt2; cnt2++; }
            if (j == qi) idx = f;
        }
        o[h] = s_comb[h*NP + idx][1] / s_comb[h*NP + idx][0];
    }

    float op[3];
    #pragma unroll
    for (int e = 0; e < 3; e++)
        op[e] = bp[e] + o[0]*Wp[e*3+0] + o[1]*Wp[e*3+1] + o[2]*Wp[e*3+2];

    float mu = (op[0] + op[1] + op[2]) * (1.0f/3.0f);
    float d0 = op[0]-mu, d1 = op[1]-mu, d2 = op[2]-mu;
    float var = (d0*d0 + d1*d1 + d2*d2) * (1.0f/3.0f);
    float inv = rsqrtf(var + EPS);
    float h2[3];
    h2[0] = d0*inv*ln2w[0] + ln2b[0];
    h2[1] = d1*inv*ln2w[1] + ln2b[1];
    h2[2] = d2*inv*ln2w[2] + ln2b[2];

    float y[3] = { op[0] + b2[0], op[1] + b2[1], op[2] + b2[2] };
    #pragma unroll
    for (int f = 0; f < 12; f++) {
        float u = b1[f] + h2[0]*W1[f*3+0] + h2[1]*W1[f*3+1] + h2[2]*W1[f*3+2];
        float su = u / (1.0f + __expf(-u));
        y[0] += su * W2[0*12 + f];
        y[1] += su * W2[1*12 + f];
        y[2] += su * W2[2*12 + f];
    }

    if (qi == 0) {
        out[b] = bg[0] + gb[0] + y[0]*Wg[0] + y[1]*Wg[1] + y[2]*Wg[2];
    } else {
        int p = qi - 1;
        out[NB + b*9 + p] = bc[0] + y[0]*Wc[0] + y[1]*Wc[1] + y[2]*Wc[2] + cb[p];
    }
}

extern "C" void kernel_launch(void* const* d_in, const int* in_sizes, int n_in,
                              void* d_out, int out_size)
{
    const float* x    = (const float*)d_in[0];
    const float* qp   = (const float*)d_in[1];
    const float* ln1w = (const float*)d_in[2];
    const float* ln1b = (const float*)d_in[3];
    const float* Wk   = (const float*)d_in[4];
    const float* bk   = (const float*)d_in[5];
    const float* Wv   = (const float*)d_in[6];
    const float* bv   = (const float*)d_in[7];
    const float* Wp   = (const float*)d_in[8];
    const float* bp   = (const float*)d_in[9];
    const float* ln2w = (const float*)d_in[10];
    const float* ln2b = (const float*)d_in[11];
    const float* W1   = (const float*)d_in[12];
    const float* b1   = (const float*)d_in[13];
    const float* W2   = (const float*)d_in[14];
    const float* b2   = (const float*)d_in[15];
    const float* Wg   = (const float*)d_in[16];
    const float* bg   = (const float*)d_in[17];
    const float* Wc   = (const float*)d_in[18];
    const float* bc   = (const float*)d_in[19];
    const float* gb   = (const float*)d_in[20];
    const float* cb   = (const float*)d_in[21];
    float* out = (float*)d_out;

    k_fast<<<NB*BPB, THREADS>>>(x, qp, ln1w, ln1b, Wk, bk, Wv, bv,
                                Wp, bp, ln2w, ln2b, W1, b1, W2, b2,
                                Wg, bg, Wc, bc, gb, cb, out);

    // PDL launch of the fallback: overlaps its early-exit under k_fast.
    cudaLaunchConfig_t cfg = {};
    cfg.gridDim  = dim3(NB*BPB_G, 1, 1);
    cfg.blockDim = dim3(THR_G, 1, 1);
    cudaLaunchAttribute attrs[1];
    attrs[0].id = cudaLaunchAttributeProgrammaticStreamSerialization;
    attrs[0].val.programmaticStreamSerializationAllowed = 1;
    cfg.attrs = attrs;
    cfg.numAttrs = 1;
    cudaError_t err = cudaLaunchKernelEx(&cfg, k_generic,
        x, qp, ln1w, ln1b, Wk, bk, Wv, bv, Wp, bp, ln2w, ln2b,
        W1, b1, W2, b2, Wg, bg, Wc, bc, gb, cb, out);
    if (err != cudaSuccess) {
        // defensive: plain serialized launch if PDL unsupported
        k_generic<<<NB*BPB_G, THR_G>>>(x, qp, ln1w, ln1b, Wk, bk, Wv, bv,
                                       Wp, bp, ln2w, ln2b, W1, b1, W2, b2,
                                       Wg, bg, Wc, bc, gb, cb, out);
    }
}

// round 6
// speedup vs baseline: 3.2579x; 1.1065x over previous
#include <cuda_runtime.h>
#include <math.h>

#define NB 16
#define NPIX (512*512)
#define NP 10
#define NSLOT 30
#define EPS 1e-5f
#define LOG2E 1.4426950408889634f

// single-wave geometry: 16 batches x 37 blocks = 592 = 148 SMs x 4 blocks
#define BPB 37
#define THREADS 256
#define NWARP (THREADS/32)
#define GPB (NPIX/4)
#define FSTRIDE (BPB*THREADS)        // 9472
#define FITERS 7                     // ceil(65536/9472)

typedef unsigned long long ull;

// ---- scratch (graph-capture safe device globals) ----
__device__ __align__(16) float g_fast[NB][BPB][12];
__device__ int   g_cnt[NB];                      // fast tickets (self-reset)
__device__ float g_part[NB][BPB][NSLOT][3];      // generic partials
__device__ int   g_cnt2[NB];                     // generic tickets

// ---------------- packed f32x2 helpers ----------------
__device__ __forceinline__ ull PK(float lo, float hi) {
    ull r; asm("mov.b64 %0,{%1,%2};" : "=l"(r) : "f"(lo), "f"(hi)); return r;
}
__device__ __forceinline__ void UPK(float& lo, float& hi, ull v) {
    asm("mov.b64 {%0,%1},%2;" : "=f"(lo), "=f"(hi) : "l"(v));
}
__device__ __forceinline__ ull ADD2(ull a, ull b) {
    ull r; asm("add.rn.f32x2 %0,%1,%2;" : "=l"(r) : "l"(a), "l"(b)); return r;
}
__device__ __forceinline__ ull MUL2(ull a, ull b) {
    ull r; asm("mul.rn.f32x2 %0,%1,%2;" : "=l"(r) : "l"(a), "l"(b)); return r;
}
__device__ __forceinline__ ull FMA2(ull a, ull b, ull c) {
    ull r; asm("fma.rn.f32x2 %0,%1,%2,%3;" : "=l"(r) : "l"(a), "l"(b), "l"(c)); return r;
}
__device__ __forceinline__ float ex2f(float a) {
    float r; asm("ex2.approx.f32 %0, %1;" : "=f"(r) : "f"(a)); return r;
}

__device__ __forceinline__ int fast_coeffs(
    const float* __restrict__ qp, const float* __restrict__ ln1w,
    const float* __restrict__ ln1b, const float* __restrict__ Wk,
    const float* __restrict__ bk, float g0[3], float g1[3])
{
    int ok = 1;
    #pragma unroll
    for (int h = 0; h < 3; h++) {
        float q = qp[h];
        #pragma unroll
        for (int j = 1; j < NP; j++) ok &= (qp[j*3 + h] == q);
        float F[3]; float n2 = 0.f;
        #pragma unroll
        for (int c = 0; c < 3; c++) {
            F[c] = q * Wk[h*3+c] * ln1w[c];
            n2 += F[c] * F[c];
        }
        float r = 1.7320509f * sqrtf(n2);
        ok &= (2.f * r <= 60.f);
        g0[h] = (F[0] - F[2]) * LOG2E;
        g1[h] = (F[1] - F[2]) * LOG2E;
    }
    return ok;
}

// shared epilogue: o[3] -> Wp -> LN2 -> SiLU FFN -> heads; writes row qi of batch b
__device__ __forceinline__ void epilogue_one(
    int b, int qi, float o0, float o1, float o2,
    const float* __restrict__ Wp, const float* __restrict__ bp,
    const float* __restrict__ ln2w, const float* __restrict__ ln2b,
    const float* __restrict__ W1, const float* __restrict__ b1,
    const float* __restrict__ W2, const float* __restrict__ b2,
    const float* __restrict__ Wg, const float* __restrict__ bg,
    const float* __restrict__ Wc, const float* __restrict__ bc,
    const float* __restrict__ gb, const float* __restrict__ cb,
    float* __restrict__ out)
{
    float op[3];
    #pragma unroll
    for (int e = 0; e < 3; e++)
        op[e] = bp[e] + o0*Wp[e*3+0] + o1*Wp[e*3+1] + o2*Wp[e*3+2];

    float mu = (op[0] + op[1] + op[2]) * (1.0f/3.0f);
    float d0 = op[0]-mu, d1 = op[1]-mu, d2 = op[2]-mu;
    float var = (d0*d0 + d1*d1 + d2*d2) * (1.0f/3.0f);
    float inv = rsqrtf(var + EPS);
    float h2[3];
    h2[0] = d0*inv*ln2w[0] + ln2b[0];
    h2[1] = d1*inv*ln2w[1] + ln2b[1];
    h2[2] = d2*inv*ln2w[2] + ln2b[2];

    float y[3] = { op[0] + b2[0], op[1] + b2[1], op[2] + b2[2] };
    #pragma unroll
    for (int f = 0; f < 12; f++) {
        float u = b1[f] + h2[0]*W1[f*3+0] + h2[1]*W1[f*3+1] + h2[2]*W1[f*3+2];
        float su = u / (1.0f + __expf(-u));
        y[0] += su * W2[0*12 + f];
        y[1] += su * W2[1*12 + f];
        y[2] += su * W2[2*12 + f];
    }
    if (qi == 0) {
        out[b] = bg[0] + gb[0] + y[0]*Wg[0] + y[1]*Wg[1] + y[2]*Wg[2];
    } else {
        int p = qi - 1;
        out[NB + b*9 + p] = bc[0] + y[0]*Wc[0] + y[1]*Wc[1] + y[2]*Wc[2] + cb[p];
    }
}

// ---------------------------------------------------------------------------
// GENERIC cold path (never runs on the real input; __noinline__ so its heavy
// register/local usage cannot disturb the hot path's allocation).
// Exact online-softmax over all 30 (head, query) slots, same 592-block grid.
// ---------------------------------------------------------------------------
__device__ __noinline__ void generic_path(
    const float* __restrict__ x, const float* __restrict__ qp,
    const float* __restrict__ ln1w, const float* __restrict__ ln1b,
    const float* __restrict__ Wk, const float* __restrict__ bk,
    const float* __restrict__ Wv, const float* __restrict__ bv,
    const float* __restrict__ Wp, const float* __restrict__ bp,
    const float* __restrict__ ln2w, const float* __restrict__ ln2b,
    const float* __restrict__ W1, const float* __restrict__ b1,
    const float* __restrict__ W2, const float* __restrict__ b2,
    const float* __restrict__ Wg, const float* __restrict__ bg,
    const float* __restrict__ Wc, const float* __restrict__ bc,
    const float* __restrict__ gb, const float* __restrict__ cb,
    float* __restrict__ out)
{
    __shared__ float s_da[3][NP];
    __shared__ int   s_cnt[3];
    __shared__ float s_red[NWARP][NSLOT][3];
    __shared__ float s_comb[NSLOT][2];
    __shared__ int   s_win;

    const int b    = blockIdx.x / BPB;
    const int blk  = blockIdx.x - b * BPB;
    const int t    = threadIdx.x;
    const int lane = t & 31;
    const int warp = t >> 5;

    if (t == 0) {
        for (int h = 0; h < 3; h++) {
            int cnt = 0;
            for (int j = 0; j < NP; j++) {
                float v = qp[j*3 + h];
                int f = -1;
                for (int c = 0; c < cnt; c++) if (s_da[h][c] == v) { f = c; break; }
                if (f < 0) { s_da[h][cnt] = v; cnt++; }
            }
            for (int j = cnt; j < NP; j++) s_da[h][j] = 0.0f;
            s_cnt[h] = cnt;
        }
    }
    __syncthreads();

    float Ak[3][3], Bk[3], Av[3][3], Bv[3];
    #pragma unroll
    for (int h = 0; h < 3; h++) {
        float sk = bk[h], sv0 = bv[h];
        #pragma unroll
        for (int c = 0; c < 3; c++) {
            float wkv = Wk[h*3+c], wvv = Wv[h*3+c];
            Ak[h][c] = wkv * ln1w[c];
            Av[h][c] = wvv * ln1w[c];
            sk  += wkv * ln1b[c];
            sv0 += wvv * ln1b[c];
        }
        Bk[h] = sk; Bv[h] = sv0;
    }

    float da[3][NP]; int cnt[3];
    #pragma unroll
    for (int h = 0; h < 3; h++) {
        cnt[h] = s_cnt[h];
        #pragma unroll
        for (int j = 0; j < NP; j++) da[h][j] = s_da[h][j];
    }

    float am[3][NP], as[3][NP], avv[3][NP];
    #pragma unroll
    for (int h = 0; h < 3; h++)
        #pragma unroll
        for (int j = 0; j < NP; j++) { am[h][j] = -1e30f; as[h][j] = 0.f; avv[h][j] = 0.f; }

    const float4* p0 = (const float4*)(x + (size_t)b * 3 * NPIX);
    const float4* p1 = p0 + GPB;
    const float4* p2 = p0 + 2*GPB;
    const int gbase = blk*THREADS + t;

    for (int it = 0; it < FITERS; it++) {
        int g = gbase + it*FSTRIDE;
        if (g >= GPB) break;
        float4 r0 = p0[g], r1 = p1[g], r2 = p2[g];
        float c0[4] = {r0.x, r0.y, r0.z, r0.w};
        float c1[4] = {r1.x, r1.y, r1.z, r1.w};
        float c2[4] = {r2.x, r2.y, r2.z, r2.w};
        #pragma unroll
        for (int e = 0; e < 4; e++) {
            float x0 = c0[e], x1 = c1[e], x2 = c2[e];
            float mu  = (x0 + x1 + x2) * (1.0f/3.0f);
            float d0 = x0 - mu, d1 = x1 - mu, d2 = x2 - mu;
            float var = (d0*d0 + d1*d1 + d2*d2) * (1.0f/3.0f);
            float inv = rsqrtf(var + EPS);
            float kh[3], vh[3];
            #pragma unroll
            for (int h = 0; h < 3; h++) {
                kh[h] = fmaf(inv, d0*Ak[h][0] + d1*Ak[h][1] + d2*Ak[h][2], Bk[h]);
                vh[h] = fmaf(inv, d0*Av[h][0] + d1*Av[h][1] + d2*Av[h][2], Bv[h]);
            }
            #pragma unroll
            for (int h = 0; h < 3; h++) {
                #pragma unroll
                for (int j = 0; j < NP; j++) {
                    if (j >= cnt[h]) break;
                    float l = da[h][j] * kh[h];
                    if (l > am[h][j]) {
                        float cc = __expf(am[h][j] - l);
                        as[h][j]  = fmaf(as[h][j], cc, 1.0f);
                        avv[h][j] = fmaf(avv[h][j], cc, vh[h]);
                        am[h][j] = l;
                    } else {
                        float e2 = __expf(l - am[h][j]);
                        as[h][j] += e2;
                        avv[h][j] = fmaf(e2, vh[h], avv[h][j]);
                    }
                }
            }
        }
    }

    #pragma unroll
    for (int h = 0; h < 3; h++) {
        #pragma unroll
        for (int j = 0; j < NP; j++) {
            float m = am[h][j];
            float M = m;
            #pragma unroll
            for (int off = 16; off > 0; off >>= 1)
                M = fmaxf(M, __shfl_xor_sync(0xffffffffu, M, off));
            float f  = __expf(m - M);
            float s  = as[h][j] * f;
            float sv = avv[h][j] * f;
            #pragma unroll
            for (int off = 16; off > 0; off >>= 1) {
                s  += __shfl_xor_sync(0xffffffffu, s,  off);
                sv += __shfl_xor_sync(0xffffffffu, sv, off);
            }
            if (lane == 0) {
                s_red[warp][h*NP+j][0] = M;
                s_red[warp][h*NP+j][1] = s;
                s_red[warp][h*NP+j][2] = sv;
            }
        }
    }
    __syncthreads();
    if (t < NSLOT) {
        float M = -1e30f;
        #pragma unroll
        for (int w = 0; w < NWARP; w++) M = fmaxf(M, s_red[w][t][0]);
        float s = 0.f, sv = 0.f;
        #pragma unroll
        for (int w = 0; w < NWARP; w++) {
            float f = __expf(s_red[w][t][0] - M);
            s  = fmaf(s_red[w][t][1], f, s);
            sv = fmaf(s_red[w][t][2], f, sv);
        }
        g_part[b][blk][t][0] = M;
        g_part[b][blk][t][1] = s;
        g_part[b][blk][t][2] = sv;
    }
    __threadfence();
    if (t == 0) s_win = (atomicAdd(&g_cnt2[b], 1) == BPB - 1);
    __syncthreads();
    if (!s_win) return;

    // winner: combine 37 partials per slot
    for (int slot = warp; slot < NSLOT; slot += NWARP) {
        float m = g_part[b][lane][slot][0];
        float s = g_part[b][lane][slot][1];
        float sv = g_part[b][lane][slot][2];
        if (lane + 32 < BPB) {
            float m2 = g_part[b][lane+32][slot][0];
            float s2 = g_part[b][lane+32][slot][1];
            float v2 = g_part[b][lane+32][slot][2];
            float mm = fmaxf(m, m2);
            float f1 = __expf(m - mm), f2 = __expf(m2 - mm);
            s  = s*f1 + s2*f2;
            sv = sv*f1 + v2*f2;
            m = mm;
        }
        float M = m;
        #pragma unroll
        for (int off = 16; off > 0; off >>= 1)
            M = fmaxf(M, __shfl_xor_sync(0xffffffffu, M, off));
        float f = __expf(m - M);
        s *= f; sv *= f;
        #pragma unroll
        for (int off = 16; off > 0; off >>= 1) {
            s  += __shfl_xor_sync(0xffffffffu, s,  off);
            sv += __shfl_xor_sync(0xffffffffu, sv, off);
        }
        if (lane == 0) {
            s_comb[slot][0] = s;
            s_comb[slot][1] = sv;
        }
    }
    __syncthreads();

    if (t == 0) g_cnt2[b] = 0;   // reset for graph replay
    if (t >= NP) return;
    int qi = t;

    float o[3];
    #pragma unroll
    for (int h = 0; h < 3; h++) {
        float list[NP]; int cnt2 = 0; int idx = 0;
        for (int j = 0; j <= qi; j++) {
            float v2 = qp[j*3 + h];
            int f = -1;
            for (int c = 0; c < cnt2; c++) if (list[c] == v2) { f = c; break; }
            if (f < 0) { list[cnt2] = v2; f = cnt2; cnt2++; }
            if (j == qi) idx = f;
        }
        o[h] = s_comb[h*NP + idx][1] / s_comb[h*NP + idx][0];
    }
    epilogue_one(b, qi, o[0], o[1], o[2], Wp, bp, ln2w, ln2b,
                 W1, b1, W2, b2, Wg, bg, Wc, bc, gb, cb, out);
}

// ---------------------------------------------------------------------------
// Single fused kernel: fast path (packed f32x2, double-buffered loads,
// last-block combine + epilogue) with the generic path as a cold branch.
// ---------------------------------------------------------------------------
__global__ void __launch_bounds__(THREADS, 4) k_all(
    const float* __restrict__ x,  const float* __restrict__ qp,
    const float* __restrict__ ln1w, const float* __restrict__ ln1b,
    const float* __restrict__ Wk, const float* __restrict__ bk,
    const float* __restrict__ Wv, const float* __restrict__ bv,
    const float* __restrict__ Wp, const float* __restrict__ bp,
    const float* __restrict__ ln2w, const float* __restrict__ ln2b,
    const float* __restrict__ W1, const float* __restrict__ b1,
    const float* __restrict__ W2, const float* __restrict__ b2,
    const float* __restrict__ Wg, const float* __restrict__ bg,
    const float* __restrict__ Wc, const float* __restrict__ bc,
    const float* __restrict__ gb, const float* __restrict__ cb,
    float* __restrict__ out)
{
    float g0s[3], g1s[3];
    if (!fast_coeffs(qp, ln1w, ln1b, Wk, bk, g0s, g1s)) {
        generic_path(x, qp, ln1w, ln1b, Wk, bk, Wv, bv, Wp, bp, ln2w, ln2b,
                     W1, b1, W2, b2, Wg, bg, Wc, bc, gb, cb, out);
        return;
    }

    __shared__ float s_red[NWARP][12];
    __shared__ float s_o[3];
    __shared__ int   s_win;

    const int b    = blockIdx.x / BPB;
    const int blk  = blockIdx.x - b * BPB;
    const int t    = threadIdx.x;
    const int lane = t & 31;
    const int warp = t >> 5;

    ull G0[3], G1[3];
    #pragma unroll
    for (int h = 0; h < 3; h++) { G0[h] = PK(g0s[h], g0s[h]); G1[h] = PK(g1s[h], g1s[h]); }
    const ull nthird2 = PK(-1.0f/3.0f, -1.0f/3.0f);
    const ull twoth2  = PK( 2.0f/3.0f,  2.0f/3.0f);
    const ull eps2    = PK(EPS, EPS);

    ull S[3], T0[3], T1[3];
    #pragma unroll
    for (int h = 0; h < 3; h++) { S[h] = 0ull; T0[h] = 0ull; T1[h] = 0ull; }

    const float4* p0 = (const float4*)(x + (size_t)b * 3 * NPIX);
    const float4* p1 = p0 + GPB;
    const float4* p2 = p0 + 2*GPB;

    int g = blk * THREADS + t;
    bool v = (g < GPB);
    float4 a0, a1, a2;
    if (v) { a0 = __ldcs(p0 + g); a1 = __ldcs(p1 + g); a2 = __ldcs(p2 + g); }

    #pragma unroll
    for (int it = 0; it < FITERS; it++) {
        int gn = g + FSTRIDE;
        bool vn = (it + 1 < FITERS) && (gn < GPB);
        float4 n0, n1, n2;
        if (vn) { n0 = __ldcs(p0 + gn); n1 = __ldcs(p1 + gn); n2 = __ldcs(p2 + gn); }
        if (v) {
            #pragma unroll
            for (int pr = 0; pr < 2; pr++) {
                float xa = pr ? a0.z : a0.x, ya = pr ? a0.w : a0.y;
                float xb = pr ? a1.z : a1.x, yb = pr ? a1.w : a1.y;
                float xc = pr ? a2.z : a2.x, yc = pr ? a2.w : a2.y;
                ull c0 = PK(xa, ya), c1 = PK(xb, yb), c2 = PK(xc, yc);
                ull sm = ADD2(ADD2(c0, c1), c2);
                ull nmu = MUL2(sm, nthird2);
                ull d0 = ADD2(c0, nmu);
                ull d1 = ADD2(c1, nmu);
                ull qq = MUL2(d0, d0);
                ull tq = FMA2(d1, d1, qq);
                ull t2 = FMA2(d0, d1, tq);
                ull vg = FMA2(t2, twoth2, eps2);
                float vl, vh; UPK(vl, vh, vg);
                ull inv2 = PK(rsqrtf(vl), rsqrtf(vh));
                ull u0 = MUL2(d0, inv2), u1 = MUL2(d1, inv2);
                #pragma unroll
                for (int h = 0; h < 3; h++) {
                    ull arg = FMA2(u1, G1[h], MUL2(u0, G0[h]));
                    float al, ah; UPK(al, ah, arg);
                    ull ee = PK(ex2f(al), ex2f(ah));
                    S[h]  = ADD2(S[h], ee);
                    T0[h] = FMA2(ee, u0, T0[h]);
                    T1[h] = FMA2(ee, u1, T1[h]);
                }
            }
        }
        a0 = n0; a1 = n1; a2 = n2;
        g = gn; v = vn;
    }

    float acc[12];
    #pragma unroll
    for (int h = 0; h < 3; h++) {
        float sl, sh, t0l, t0h, t1l, t1h;
        UPK(sl, sh, S[h]); UPK(t0l, t0h, T0[h]); UPK(t1l, t1h, T1[h]);
        float Sv = sl + sh, T0v = t0l + t0h, T1v = t1l + t1h;
        acc[h*4+0] = Sv;
        acc[h*4+1] = T0v;
        acc[h*4+2] = T1v;
        acc[h*4+3] = -(T0v + T1v);
    }
    #pragma unroll
    for (int f = 0; f < 12; f++) {
        float vv = acc[f];
        #pragma unroll
        for (int off = 16; off > 0; off >>= 1)
            vv += __shfl_xor_sync(0xffffffffu, vv, off);
        acc[f] = vv;
    }
    if (lane == 0) {
        #pragma unroll
        for (int f = 0; f < 12; f++) s_red[warp][f] = acc[f];
    }
    __syncthreads();
    if (t < 12) {
        float vv = 0.f;
        #pragma unroll
        for (int w = 0; w < NWARP; w++) vv += s_red[w][t];
        g_fast[b][blk][t] = vv;
    }
    __threadfence();
    if (t == 0) s_win = (atomicAdd(&g_cnt[b], 1) == BPB - 1);
    __syncthreads();
    if (!s_win) return;

    // winner: combine 37 partials per head, o[h] = SV/S
    if (warp < 3) {
        float r0 = 0.f, r1 = 0.f, r2 = 0.f, r3 = 0.f;
        {
            float4 p = __ldcg((const float4*)&g_fast[b][lane][warp*4]);
            r0 = p.x; r1 = p.y; r2 = p.z; r3 = p.w;
        }
        if (lane + 32 < BPB) {
            float4 p = __ldcg((const float4*)&g_fast[b][lane+32][warp*4]);
            r0 += p.x; r1 += p.y; r2 += p.z; r3 += p.w;
        }
        #pragma unroll
        for (int off = 16; off > 0; off >>= 1) {
            r0 += __shfl_xor_sync(0xffffffffu, r0, off);
            r1 += __shfl_xor_sync(0xffffffffu, r1, off);
            r2 += __shfl_xor_sync(0xffffffffu, r2, off);
            r3 += __shfl_xor_sync(0xffffffffu, r3, off);
        }
        if (lane == 0) {
            int h = warp;
            float Bvh = bv[h];
            float Av0 = Wv[h*3+0] * ln1w[0];
            float Av1 = Wv[h*3+1] * ln1w[1];
            float Av2 = Wv[h*3+2] * ln1w[2];
            #pragma unroll
            for (int c = 0; c < 3; c++) Bvh += Wv[h*3+c] * ln1b[c];
            float SV = Bvh*r0 + Av0*r1 + Av1*r2 + Av2*r3;
            s_o[h] = SV / r0;
        }
    }
    __syncthreads();
    if (t == 0) {
        g_cnt[b] = 0;   // reset for next graph replay

        float o0 = s_o[0], o1 = s_o[1], o2 = s_o[2];
        float op[3];
        #pragma unroll
        for (int e = 0; e < 3; e++)
            op[e] = bp[e] + o0*Wp[e*3+0] + o1*Wp[e*3+1] + o2*Wp[e*3+2];

        float mu = (op[0] + op[1] + op[2]) * (1.0f/3.0f);
        float d0 = op[0]-mu, d1 = op[1]-mu, d2 = op[2]-mu;
        float var = (d0*d0 + d1*d1 + d2*d2) * (1.0f/3.0f);
        float inv = rsqrtf(var + EPS);
        float h2[3];
        h2[0] = d0*inv*ln2w[0] + ln2b[0];
        h2[1] = d1*inv*ln2w[1] + ln2b[1];
        h2[2] = d2*inv*ln2w[2] + ln2b[2];

        float y[3] = { op[0] + b2[0], op[1] + b2[1], op[2] + b2[2] };
        #pragma unroll
        for (int f = 0; f < 12; f++) {
            float u = b1[f] + h2[0]*W1[f*3+0] + h2[1]*W1[f*3+1] + h2[2]*W1[f*3+2];
            float su = u / (1.0f + __expf(-u));
            y[0] += su * W2[0*12 + f];
            y[1] += su * W2[1*12 + f];
            y[2] += su * W2[2*12 + f];
        }
        out[b] = bg[0] + gb[0] + y[0]*Wg[0] + y[1]*Wg[1] + y[2]*Wg[2];
        float colbase = bc[0] + y[0]*Wc[0] + y[1]*Wc[1] + y[2]*Wc[2];
        #pragma unroll
        for (int p = 0; p < 9; p++)
            out[NB + b*9 + p] = colbase + cb[p];
    }
}

extern "C" void kernel_launch(void* const* d_in, const int* in_sizes, int n_in,
                              void* d_out, int out_size)
{
    const float* x    = (const float*)d_in[0];
    const float* qp   = (const float*)d_in[1];
    const float* ln1w = (const float*)d_in[2];
    const float* ln1b = (const float*)d_in[3];
    const float* Wk   = (const float*)d_in[4];
    const float* bk   = (const float*)d_in[5];
    const float* Wv   = (const float*)d_in[6];
    const float* bv   = (const float*)d_in[7];
    const float* Wp   = (const float*)d_in[8];
    const float* bp   = (const float*)d_in[9];
    const float* ln2w = (const float*)d_in[10];
    const float* ln2b = (const float*)d_in[11];
    const float* W1   = (const float*)d_in[12];
    const float* b1   = (const float*)d_in[13];
    const float* W2   = (const float*)d_in[14];
    const float* b2   = (const float*)d_in[15];
    const float* Wg   = (const float*)d_in[16];
    const float* bg   = (const float*)d_in[17];
    const float* Wc   = (const float*)d_in[18];
    const float* bc   = (const float*)d_in[19];
    const float* gb   = (const float*)d_in[20];
    const float* cb   = (const float*)d_in[21];
    float* out = (float*)d_out;

    k_all<<<NB*BPB, THREADS>>>(x, qp, ln1w, ln1b, Wk, bk, Wv, bv,
                               Wp, bp, ln2w, ln2b, W1, b1, W2, b2,
                               Wg, bg, Wc, bc, gb, cb, out);
}